// round 9
// baseline (speedup 1.0000x reference)
#include <cuda_runtime.h>
#include <cuda_bf16.h>
#include <math.h>
#include <stdint.h>

// ---------------- problem constants ----------------
#define DEPTH   12
#define DIMC    768
#define HEADS   12
#define MLPD    3072
#define NCLS    1000
#define NTOK    197
#define NPATCH  196
#define BATCH   32
#define HDIM    64
#define GRD     14
#define BNROWS  (BATCH*NTOK)     // 6304
#define PROWS   (BATCH*NPATCH)   // 6272
#define H3      (3*DIMC)         // 2304

// ---------------- scratch (fp32) ----------------
__device__ float g_pe[PROWS*DIMC];
__device__ float g_t[BNROWS*DIMC];
__device__ float g_h[BNROWS*DIMC];
__device__ float g_qkv[BNROWS*H3];
__device__ float g_pooled[BATCH*DIMC];

// ---------------- scratch (bf16 hi/lo activation planes) ----------------
__device__ __nv_bfloat16 g_px_hi[PROWS*DIMC],  g_px_lo[PROWS*DIMC];
__device__ __nv_bfloat16 g_h_hi[BNROWS*DIMC],  g_h_lo[BNROWS*DIMC];
__device__ __nv_bfloat16 g_ao_hi[BNROWS*DIMC], g_ao_lo[BNROWS*DIMC];
__device__ __nv_bfloat16 g_ml_hi[BNROWS*MLPD], g_ml_lo[BNROWS*MLPD];

// ---------------- scratch (bf16 hi/lo weight planes) ----------------
__device__ __nv_bfloat16 wpe_hi[DIMC*DIMC],       wpe_lo[DIMC*DIMC];
__device__ __nv_bfloat16 wqk_hi[DEPTH*DIMC*H3],   wqk_lo[DEPTH*DIMC*H3];
__device__ __nv_bfloat16 wpr_hi[DEPTH*DIMC*DIMC], wpr_lo[DEPTH*DIMC*DIMC];
__device__ __nv_bfloat16 wf1_hi[DEPTH*DIMC*MLPD], wf1_lo[DEPTH*DIMC*MLPD];
__device__ __nv_bfloat16 wf2_hi[DEPTH*MLPD*DIMC], wf2_lo[DEPTH*MLPD*DIMC];

// ---------------- helpers ----------------
__device__ __forceinline__ uint32_t smem_u32(const void* p) {
    uint32_t a;
    asm("{ .reg .u64 t; cvta.to.shared.u64 t, %1; cvt.u32.u64 %0, t; }"
        : "=r"(a) : "l"(p));
    return a;
}
__device__ __forceinline__ uint32_t pack2(__nv_bfloat16 a, __nv_bfloat16 b) {
    return (uint32_t)__bfloat16_as_ushort(a) |
           ((uint32_t)__bfloat16_as_ushort(b) << 16);
}
__device__ __forceinline__ void ldmx4(uint32_t* r, uint32_t addr) {
    asm volatile("ldmatrix.sync.aligned.m8n8.x4.shared.b16 {%0,%1,%2,%3}, [%4];"
        : "=r"(r[0]), "=r"(r[1]), "=r"(r[2]), "=r"(r[3]) : "r"(addr));
}
__device__ __forceinline__ void ldmx4t(uint32_t* r, uint32_t addr) {
    asm volatile("ldmatrix.sync.aligned.m8n8.x4.trans.shared.b16 {%0,%1,%2,%3}, [%4];"
        : "=r"(r[0]), "=r"(r[1]), "=r"(r[2]), "=r"(r[3]) : "r"(addr));
}
__device__ __forceinline__ void mma16816(float* d, const uint32_t* a, const uint32_t* b) {
    asm volatile(
        "mma.sync.aligned.m16n8k16.row.col.f32.bf16.bf16.f32 "
        "{%0,%1,%2,%3}, {%4,%5,%6,%7}, {%8,%9}, {%0,%1,%2,%3};"
        : "+f"(d[0]), "+f"(d[1]), "+f"(d[2]), "+f"(d[3])
        : "r"(a[0]), "r"(a[1]), "r"(a[2]), "r"(a[3]), "r"(b[0]), "r"(b[1]));
}
__device__ __forceinline__ void cpa16(uint32_t dst, const void* src, bool ok) {
    asm volatile("cp.async.cg.shared.global [%0], [%1], 16, %2;"
                 :: "r"(dst), "l"(src), "r"(ok ? 16 : 0) : "memory");
}

// ---------------- smem layout per stage (bf16 units) ----------------
#define ASTR    40
#define BSTR    136
#define APLANE  10240
#define BOFF    20480
#define BPLANE  8704
#define BUFSZ   37888
#define NSTG    2
#define HM_SMEM (NSTG*BUFSZ)   // 75776 B -> with regs<=128, 2 CTAs/SM

// ---------------- weight conversion: fp32 -> bf16 hi/lo ----------------
__global__ void convert_w(const float* __restrict__ src,
                          __nv_bfloat16* __restrict__ hi,
                          __nv_bfloat16* __restrict__ lo, int n4) {
    int i = blockIdx.x * blockDim.x + threadIdx.x;
    if (i >= n4) return;
    float4 v = *(const float4*)(src + i*4);
    __nv_bfloat16 h0=__float2bfloat16(v.x), h1=__float2bfloat16(v.y);
    __nv_bfloat16 h2=__float2bfloat16(v.z), h3=__float2bfloat16(v.w);
    *(uint32_t*)(hi + i*4)     = pack2(h0, h1);
    *(uint32_t*)(hi + i*4 + 2) = pack2(h2, h3);
    *(uint32_t*)(lo + i*4)     = pack2(__float2bfloat16(v.x-__bfloat162float(h0)),
                                       __float2bfloat16(v.y-__bfloat162float(h1)));
    *(uint32_t*)(lo + i*4 + 2) = pack2(__float2bfloat16(v.z-__bfloat162float(h2)),
                                       __float2bfloat16(v.w-__bfloat162float(h3)));
}

// ============ bf16 3-split mma.sync GEMM ============
// EPI: 0=bias->f32, 1=bias+residual->f32, 2=bias+GELU->bf16 hi/lo planes
template<int EPI>
__global__ __launch_bounds__(256, 2) void hmma_gemm(
    const __nv_bfloat16* __restrict__ Ahi, const __nv_bfloat16* __restrict__ Alo,
    const __nv_bfloat16* __restrict__ Whi, const __nv_bfloat16* __restrict__ Wlo,
    const float* __restrict__ bias, const float* __restrict__ Res,
    float* __restrict__ C,
    __nv_bfloat16* __restrict__ Chi, __nv_bfloat16* __restrict__ Clo,
    int M, int N, int K)
{
    extern __shared__ char smem[];
    const uint32_t sb = smem_u32(smem);
    const int tid  = threadIdx.x;
    const int warp = tid >> 5;
    const int lane = tid & 31;
    const int mbase = blockIdx.y * 128;
    const int nbase = blockIdx.x * 128;

    const int wm = (warp & 1) * 64;
    const int wn = (warp >> 1) * 32;

    float d[4][4][4];
    #pragma unroll
    for (int i = 0; i < 4; i++)
        #pragma unroll
        for (int j = 0; j < 4; j++)
            #pragma unroll
            for (int r = 0; r < 4; r++) d[i][j][r] = 0.f;

    const int nch = K >> 5;

    #define ISSUE(c, bsel) do {                                               \
        const uint32_t dbase = sb + (uint32_t)(bsel) * BUFSZ;                 \
        const int k0 = (c) << 5;                                              \
        _Pragma("unroll")                                                     \
        for (int i = 0; i < 4; i++) {                                         \
            int t = tid + i*256;                                              \
            int p = t >> 9, idx = t & 511;                                    \
            int row = idx >> 2, seg = idx & 3;                                \
            bool ok = (mbase + row) < M;                                      \
            const __nv_bfloat16* sp = (p ? Alo : Ahi);                        \
            const __nv_bfloat16* src = ok ? sp + (size_t)(mbase+row)*K + k0 + seg*8 : sp; \
            cpa16(dbase + (uint32_t)(p*APLANE + row*80 + seg*16), src, ok);   \
        }                                                                     \
        _Pragma("unroll")                                                     \
        for (int i = 0; i < 4; i++) {                                         \
            int t = tid + i*256;                                              \
            int p = t >> 9, idx = t & 511;                                    \
            int row = idx >> 4, seg = idx & 15;                               \
            const __nv_bfloat16* src = (p ? Wlo : Whi) + (size_t)(k0+row)*N + nbase + seg*8; \
            cpa16(dbase + (uint32_t)(BOFF + p*BPLANE + row*272 + seg*16), src, true); \
        }                                                                     \
        asm volatile("cp.async.commit_group;" ::: "memory");                  \
    } while (0)

    ISSUE(0, 0);

    for (int c = 0; c < nch; ++c) {
        if (c + 1 < nch) {
            ISSUE(c + 1, (c + 1) & 1);
            asm volatile("cp.async.wait_group 1;" ::: "memory");
        } else {
            asm volatile("cp.async.wait_group 0;" ::: "memory");
        }
        __syncthreads();

        const uint32_t sbuf = sb + (uint32_t)(c & 1) * BUFSZ;
        #pragma unroll
        for (int ks = 0; ks < 2; ++ks) {
            const uint32_t aoff = sbuf +
                (uint32_t)((wm + (lane & 15))*ASTR + ks*16 + (lane >> 4)*8) * 2;
            const uint32_t boff = sbuf + BOFF +
                (uint32_t)((ks*16 + (lane & 15))*BSTR + wn + (lane >> 4)*8) * 2;

            uint32_t ahi[4][4], bhi[4][2];
            #pragma unroll
            for (int mt = 0; mt < 4; mt++) ldmx4(ahi[mt], aoff + mt*(16*ASTR*2));
            #pragma unroll
            for (int ng = 0; ng < 2; ng++) {
                uint32_t r[4];
                ldmx4t(r, boff + ng*32);
                bhi[2*ng][0]   = r[0]; bhi[2*ng][1]   = r[1];
                bhi[2*ng+1][0] = r[2]; bhi[2*ng+1][1] = r[3];
            }
            #pragma unroll
            for (int mt = 0; mt < 4; mt++)
                #pragma unroll
                for (int nt = 0; nt < 4; nt++)
                    mma16816(d[mt][nt], ahi[mt], bhi[nt]);

            {
                uint32_t blo[4][2];
                #pragma unroll
                for (int ng = 0; ng < 2; ng++) {
                    uint32_t r[4];
                    ldmx4t(r, boff + BPLANE + ng*32);
                    blo[2*ng][0]   = r[0]; blo[2*ng][1]   = r[1];
                    blo[2*ng+1][0] = r[2]; blo[2*ng+1][1] = r[3];
                }
                #pragma unroll
                for (int mt = 0; mt < 4; mt++)
                    #pragma unroll
                    for (int nt = 0; nt < 4; nt++)
                        mma16816(d[mt][nt], ahi[mt], blo[nt]);
            }
            {
                uint32_t alo[4][4];
                #pragma unroll
                for (int mt = 0; mt < 4; mt++)
                    ldmx4(alo[mt], aoff + APLANE + mt*(16*ASTR*2));
                #pragma unroll
                for (int mt = 0; mt < 4; mt++)
                    #pragma unroll
                    for (int nt = 0; nt < 4; nt++)
                        mma16816(d[mt][nt], alo[mt], bhi[nt]);
            }
        }
        __syncthreads();
    }
    #undef ISSUE

    // ---- epilogue ----
    #pragma unroll
    for (int mt = 0; mt < 4; mt++) {
        const int r0 = mbase + wm + mt*16 + (lane >> 2);
        #pragma unroll
        for (int nt = 0; nt < 4; nt++) {
            const int c0 = nbase + wn + nt*8 + (lane & 3)*2;
            const float b0 = bias[c0], b1 = bias[c0+1];
            #pragma unroll
            for (int half = 0; half < 2; half++) {
                const int row = r0 + half*8;
                if (row >= M) continue;
                float v0 = d[mt][nt][2*half+0] + b0;
                float v1 = d[mt][nt][2*half+1] + b1;
                if (EPI == 1) {
                    const float* rr = Res + (size_t)row * N + c0;
                    v0 += rr[0]; v1 += rr[1];
                }
                if (EPI == 2) {
                    v0 = 0.5f*v0*(1.f + erff(v0*0.70710678118654752f));
                    v1 = 0.5f*v1*(1.f + erff(v1*0.70710678118654752f));
                    __nv_bfloat16 h0 = __float2bfloat16(v0);
                    __nv_bfloat16 h1 = __float2bfloat16(v1);
                    *(uint32_t*)(Chi + (size_t)row * N + c0) = pack2(h0, h1);
                    *(uint32_t*)(Clo + (size_t)row * N + c0) =
                        pack2(__float2bfloat16(v0 - __bfloat162float(h0)),
                              __float2bfloat16(v1 - __bfloat162float(h1)));
                } else {
                    *(float2*)(C + (size_t)row * N + c0) = make_float2(v0, v1);
                }
            }
        }
    }
}

// ---------------- patch extraction -> bf16 hi/lo ----------------
__global__ void patchify_kernel(const float* __restrict__ x) {
    int idx = blockIdx.x * blockDim.x + threadIdx.x;
    if (idx >= PROWS * DIMC) return;
    int col = idx % DIMC;
    int row = idx / DIMC;
    int b   = row / NPATCH;
    int n   = row % NPATCH;
    int g1  = n / GRD, g2 = n % GRD;
    int c   = col >> 8;
    int p1  = (col >> 4) & 15;
    int p2  = col & 15;
    float v = x[((b*3 + c)*224 + g1*16 + p1)*224 + g2*16 + p2];
    __nv_bfloat16 h = __float2bfloat16(v);
    g_px_hi[idx] = h;
    g_px_lo[idx] = __float2bfloat16(v - __bfloat162float(h));
}

// ---------------- cls concat + pos embed ----------------
__global__ void embed_kernel(const float* __restrict__ cls,
                             const float* __restrict__ pos) {
    int idx = blockIdx.x * blockDim.x + threadIdx.x;
    if (idx >= BNROWS * DIMC) return;
    int d = idx % DIMC;
    int r = idx / DIMC;
    int b = r / NTOK;
    int n = r % NTOK;
    float v = (n == 0) ? cls[d] : g_pe[(b*NPATCH + n - 1)*DIMC + d];
    g_t[idx] = v + pos[n*DIMC + d];
}

// ---------------- layernorm -> bf16 hi/lo (+ optional fp32) ----------------
template<bool WF32>
__global__ __launch_bounds__(256) void ln_kernel(const float* __restrict__ in,
                                                 float* __restrict__ out,
                                                 __nv_bfloat16* __restrict__ ohi,
                                                 __nv_bfloat16* __restrict__ olo,
                                                 const float* __restrict__ gam,
                                                 const float* __restrict__ bet) {
    int row = blockIdx.x;
    const float* x = in + row*DIMC;
    float vals[3];
    float s = 0.f, s2 = 0.f;
    #pragma unroll
    for (int i = 0; i < 3; i++) {
        float v = x[threadIdx.x + i*256];
        vals[i] = v; s += v; s2 += v*v;
    }
    #pragma unroll
    for (int o = 16; o; o >>= 1) {
        s  += __shfl_xor_sync(0xffffffffu, s,  o);
        s2 += __shfl_xor_sync(0xffffffffu, s2, o);
    }
    __shared__ float red[18];
    int wid = threadIdx.x >> 5, lane = threadIdx.x & 31;
    if (lane == 0) { red[wid] = s; red[wid + 8] = s2; }
    __syncthreads();
    if (threadIdx.x < 32) {
        float a  = (lane < 8) ? red[lane]     : 0.f;
        float b2 = (lane < 8) ? red[lane + 8] : 0.f;
        #pragma unroll
        for (int o = 4; o; o >>= 1) {
            a  += __shfl_xor_sync(0xffffffffu, a,  o);
            b2 += __shfl_xor_sync(0xffffffffu, b2, o);
        }
        if (lane == 0) { red[16] = a; red[17] = b2; }
    }
    __syncthreads();
    float mean = red[16] * (1.f/768.f);
    float var  = red[17] * (1.f/768.f) - mean*mean;
    float inv  = rsqrtf(var + 1e-6f);
    #pragma unroll
    for (int i = 0; i < 3; i++) {
        int c = threadIdx.x + i*256;
        float v = (vals[i] - mean) * inv * gam[c] + bet[c];
        if (WF32) out[row*DIMC + c] = v;
        __nv_bfloat16 h = __float2bfloat16(v);
        ohi[row*DIMC + c] = h;
        olo[row*DIMC + c] = __float2bfloat16(v - __bfloat162float(h));
    }
}

// ---------------- SIMT sgemm (head only, M=32) ----------------
__global__ __launch_bounds__(256) void sgemm_kernel(
    const float* __restrict__ A, const float* __restrict__ B,
    const float* __restrict__ bias,
    float* __restrict__ C, int M, int N, int K)
{
    __shared__ float As[8][128];
    __shared__ float Bs[8][128];
    int tid = threadIdx.x;
    int bx = blockIdx.x, by = blockIdx.y;
    int tr = tid >> 4;
    int tc = tid & 15;

    float acc[8][8];
    #pragma unroll
    for (int i = 0; i < 8; i++)
        #pragma unroll
        for (int j = 0; j < 8; j++) acc[i][j] = 0.f;

    int aRow = tid >> 1;
    int aCol = (tid & 1) * 4;
    int bRow = tid >> 5;
    int bCol = (tid & 31) * 4;
    int gARow = by*128 + aRow;
    int gBCol = bx*128 + bCol;
    const float* Aptr = A + gARow*K + aCol;
    const float* Bptr = B + bRow*N + gBCol;
    bool aValid = (gARow < M);
    bool bValid = (gBCol < N);

    for (int k0 = 0; k0 < K; k0 += 8) {
        float4 av = aValid ? *(const float4*)(Aptr + k0)
                           : make_float4(0.f,0.f,0.f,0.f);
        float4 bv = bValid ? *(const float4*)(Bptr + k0*N)
                           : make_float4(0.f,0.f,0.f,0.f);
        As[aCol+0][aRow] = av.x;
        As[aCol+1][aRow] = av.y;
        As[aCol+2][aRow] = av.z;
        As[aCol+3][aRow] = av.w;
        *(float4*)&Bs[bRow][bCol] = bv;
        __syncthreads();
        #pragma unroll
        for (int kk = 0; kk < 8; kk++) {
            float a[8], b[8];
            #pragma unroll
            for (int i = 0; i < 8; i++) a[i] = As[kk][tr*8 + i];
            #pragma unroll
            for (int j = 0; j < 8; j++) b[j] = Bs[kk][tc*8 + j];
            #pragma unroll
            for (int i = 0; i < 8; i++)
                #pragma unroll
                for (int j = 0; j < 8; j++)
                    acc[i][j] += a[i] * b[j];
        }
        __syncthreads();
    }

    #pragma unroll
    for (int i = 0; i < 8; i++) {
        int row = by*128 + tr*8 + i;
        if (row >= M) continue;
        #pragma unroll
        for (int j = 0; j < 8; j++) {
            int col = bx*128 + tc*8 + j;
            if (col >= N) continue;
            C[row*N + col] = acc[i][j] + bias[col];
        }
    }
}

// ---------------- attention (optimized SIMT) ----------------
#define KTSTR 202
#define ATTN_F (64*KTSTR + NTOK*64 + 8*200 + 8*64)
#define ATTN_SMEM (ATTN_F*4)

__global__ __launch_bounds__(256, 2) void attention_kernel(const float* __restrict__ mask) {
    extern __shared__ float sm[];
    float* Kt = sm;                    // 64 x KTSTR
    float* Vs = Kt + 64*KTSTR;         // 197 rows x 64 floats (float2-paired)
    float* Ps = Vs + NTOK*64;          // 8 x 200
    float* Qs = Ps + 8*200;            // 8 x 64

    int bh = blockIdx.x;
    int b = bh / HEADS, h = bh % HEADS;
    int tid = threadIdx.x, warp = tid >> 5, lane = tid & 31;
    const float scale = 0.125f;
    int base = (b*NTOK)*H3 + h*HDIM;

    for (int idx = tid; idx < NTOK*HDIM; idx += 256) {
        int j = idx >> 6, d = idx & 63;
        Kt[d*KTSTR + j] = g_qkv[base + j*H3 + DIMC + d];
        Vs[j*64 + (d & 31)*2 + (d >> 5)] = g_qkv[base + j*H3 + 2*DIMC + d];
    }
    __syncthreads();

    for (int r = warp; r < NTOK; r += 8) {
        Qs[warp*64 + lane]      = g_qkv[base + r*H3 + lane];
        Qs[warp*64 + lane + 32] = g_qkv[base + r*H3 + lane + 32];
        __syncwarp();
        float q[64];
        #pragma unroll
        for (int d = 0; d < 64; d++) q[d] = Qs[warp*64 + d];

        float2 sp[4];
        float mx = -1e30f;
        #pragma unroll
        for (int jj = 0; jj < 4; jj++) {
            int j0 = jj*64 + 2*lane;
            bool v0 = j0 < NTOK, v1 = (j0 + 1) < NTOK;
            float s0 = -1e30f, s1 = -1e30f;
            if (v0) {
                float a0 = 0.f, a1 = 0.f;
                #pragma unroll
                for (int d = 0; d < 64; d++) {
                    float2 kk = *(const float2*)(Kt + d*KTSTR + j0);
                    a0 += q[d] * kk.x;
                    a1 += q[d] * kk.y;
                }
                s0 = a0 * scale * mask[r*NTOK + j0];
                mx = fmaxf(mx, s0);
                if (v1) {
                    s1 = a1 * scale * mask[r*NTOK + j0 + 1];
                    mx = fmaxf(mx, s1);
                }
            }
            sp[jj] = make_float2(s0, s1);
        }
        #pragma unroll
        for (int o = 16; o; o >>= 1)
            mx = fmaxf(mx, __shfl_xor_sync(0xffffffffu, mx, o));

        float sum = 0.f;
        #pragma unroll
        for (int jj = 0; jj < 4; jj++) {
            float p0 = expf(sp[jj].x - mx);
            float p1 = expf(sp[jj].y - mx);
            sp[jj] = make_float2(p0, p1);
            sum += p0 + p1;
        }
        #pragma unroll
        for (int o = 16; o; o >>= 1)
            sum += __shfl_xor_sync(0xffffffffu, sum, o);
        float rinv = 1.f / sum;

        #pragma unroll
        for (int jj = 0; jj < 4; jj++) {
            int j0 = jj*64 + 2*lane;
            if (j0 < NTOK)     Ps[warp*200 + j0]     = sp[jj].x * rinv;
            if (j0 + 1 < NTOK) Ps[warp*200 + j0 + 1] = sp[jj].y * rinv;
        }
        __syncwarp();

        float o0 = 0.f, o1 = 0.f;
        #pragma unroll 4
        for (int j = 0; j < NTOK; j++) {
            float p = Ps[warp*200 + j];
            float2 vv = *(const float2*)(Vs + j*64 + 2*lane);
            o0 += p * vv.x;
            o1 += p * vv.y;
        }
        int orow = (b*NTOK + r)*DIMC + h*HDIM;
        __nv_bfloat16 h0 = __float2bfloat16(o0);
        __nv_bfloat16 h1 = __float2bfloat16(o1);
        g_ao_hi[orow + lane]      = h0;
        g_ao_hi[orow + lane + 32] = h1;
        g_ao_lo[orow + lane]      = __float2bfloat16(o0 - __bfloat162float(h0));
        g_ao_lo[orow + lane + 32] = __float2bfloat16(o1 - __bfloat162float(h1));
    }
}

// ---------------- gather cls rows ----------------
__global__ void gather_cls_kernel() {
    int idx = blockIdx.x * blockDim.x + threadIdx.x;
    if (idx >= BATCH * DIMC) return;
    int b = idx / DIMC, d = idx % DIMC;
    g_pooled[idx] = g_h[(b*NTOK)*DIMC + d];
}

// ---------------- host driver ----------------
static inline dim3 tc_grid(int M, int N) {
    return dim3(N / 128, (M + 127) / 128);
}

#define SYMADDR(var, sym) cudaGetSymbolAddress((void**)&var, sym)

extern "C" void kernel_launch(void* const* d_in, const int* in_sizes, int n_in,
                              void* d_out, int out_size) {
    (void)in_sizes; (void)n_in; (void)out_size;
    const float* x       = (const float*)d_in[0];
    const float* cp_mask = (const float*)d_in[1];
    const float* patch_w = (const float*)d_in[2];
    const float* patch_b = (const float*)d_in[3];
    const float* cls     = (const float*)d_in[4];
    const float* pos     = (const float*)d_in[5];
    const float* ln1_g   = (const float*)d_in[6];
    const float* ln1_b   = (const float*)d_in[7];
    const float* qkv_w   = (const float*)d_in[8];
    const float* qkv_b   = (const float*)d_in[9];
    const float* proj_w  = (const float*)d_in[10];
    const float* proj_b  = (const float*)d_in[11];
    const float* ln2_g   = (const float*)d_in[12];
    const float* ln2_b   = (const float*)d_in[13];
    const float* fc1_w   = (const float*)d_in[14];
    const float* fc1_b   = (const float*)d_in[15];
    const float* fc2_w   = (const float*)d_in[16];
    const float* fc2_b   = (const float*)d_in[17];
    const float* normf_g = (const float*)d_in[18];
    const float* normf_b = (const float*)d_in[19];
    const float* head_w  = (const float*)d_in[20];
    const float* head_b  = (const float*)d_in[21];
    float* out = (float*)d_out;

    float *p_pe, *p_t, *p_h, *p_qkv, *p_pooled;
    SYMADDR(p_pe, g_pe); SYMADDR(p_t, g_t); SYMADDR(p_h, g_h);
    SYMADDR(p_qkv, g_qkv); SYMADDR(p_pooled, g_pooled);

    __nv_bfloat16 *px_hi, *px_lo, *h_hi, *h_lo, *ao_hi, *ao_lo, *ml_hi, *ml_lo;
    SYMADDR(px_hi, g_px_hi); SYMADDR(px_lo, g_px_lo);
    SYMADDR(h_hi, g_h_hi);   SYMADDR(h_lo, g_h_lo);
    SYMADDR(ao_hi, g_ao_hi); SYMADDR(ao_lo, g_ao_lo);
    SYMADDR(ml_hi, g_ml_hi); SYMADDR(ml_lo, g_ml_lo);

    __nv_bfloat16 *pe_hi, *pe_lo, *qk_hi, *qk_lo, *pr_hi, *pr_lo,
                  *f1_hi, *f1_lo, *f2_hi, *f2_lo;
    SYMADDR(pe_hi, wpe_hi); SYMADDR(pe_lo, wpe_lo);
    SYMADDR(qk_hi, wqk_hi); SYMADDR(qk_lo, wqk_lo);
    SYMADDR(pr_hi, wpr_hi); SYMADDR(pr_lo, wpr_lo);
    SYMADDR(f1_hi, wf1_hi); SYMADDR(f1_lo, wf1_lo);
    SYMADDR(f2_hi, wf2_hi); SYMADDR(f2_lo, wf2_lo);

    cudaFuncSetAttribute(attention_kernel,
                         cudaFuncAttributeMaxDynamicSharedMemorySize, (int)ATTN_SMEM);
    cudaFuncSetAttribute(hmma_gemm<0>,
                         cudaFuncAttributeMaxDynamicSharedMemorySize, HM_SMEM);
    cudaFuncSetAttribute(hmma_gemm<1>,
                         cudaFuncAttributeMaxDynamicSharedMemorySize, HM_SMEM);
    cudaFuncSetAttribute(hmma_gemm<2>,
                         cudaFuncAttributeMaxDynamicSharedMemorySize, HM_SMEM);

    // ---- weight pre-conversion (bulk, once per launch) ----
    {
        int n4;
        n4 = (DIMC*DIMC)/4;
        convert_w<<<(n4+255)/256, 256>>>(patch_w, pe_hi, pe_lo, n4);
        n4 = (DEPTH*DIMC*H3)/4;
        convert_w<<<(n4+255)/256, 256>>>(qkv_w, qk_hi, qk_lo, n4);
        n4 = (DEPTH*DIMC*DIMC)/4;
        convert_w<<<(n4+255)/256, 256>>>(proj_w, pr_hi, pr_lo, n4);
        n4 = (DEPTH*DIMC*MLPD)/4;
        convert_w<<<(n4+255)/256, 256>>>(fc1_w, f1_hi, f1_lo, n4);
        n4 = (DEPTH*MLPD*DIMC)/4;
        convert_w<<<(n4+255)/256, 256>>>(fc2_w, f2_hi, f2_lo, n4);
    }

    patchify_kernel<<<(PROWS*DIMC + 255)/256, 256>>>(x);
    hmma_gemm<0><<<tc_grid(PROWS, DIMC), 256, HM_SMEM>>>(
        px_hi, px_lo, pe_hi, pe_lo, patch_b, nullptr,
        p_pe, nullptr, nullptr, PROWS, DIMC, DIMC);
    embed_kernel<<<(BNROWS*DIMC + 255)/256, 256>>>(cls, pos);

    for (int i = 0; i < DEPTH; i++) {
        ln_kernel<false><<<BNROWS, 256>>>(p_t, nullptr, h_hi, h_lo,
                                          ln1_g + i*DIMC, ln1_b + i*DIMC);
        hmma_gemm<0><<<tc_grid(BNROWS, H3), 256, HM_SMEM>>>(
            h_hi, h_lo, qk_hi + (size_t)i*DIMC*H3, qk_lo + (size_t)i*DIMC*H3,
            qkv_b + i*H3, nullptr, p_qkv, nullptr, nullptr, BNROWS, H3, DIMC);
        attention_kernel<<<BATCH*HEADS, 256, ATTN_SMEM>>>(cp_mask);
        hmma_gemm<1><<<tc_grid(BNROWS, DIMC), 256, HM_SMEM>>>(
            ao_hi, ao_lo, pr_hi + (size_t)i*DIMC*DIMC, pr_lo + (size_t)i*DIMC*DIMC,
            proj_b + i*DIMC, p_t, p_t, nullptr, nullptr, BNROWS, DIMC, DIMC);
        ln_kernel<false><<<BNROWS, 256>>>(p_t, nullptr, h_hi, h_lo,
                                          ln2_g + i*DIMC, ln2_b + i*DIMC);
        hmma_gemm<2><<<tc_grid(BNROWS, MLPD), 256, HM_SMEM>>>(
            h_hi, h_lo, f1_hi + (size_t)i*DIMC*MLPD, f1_lo + (size_t)i*DIMC*MLPD,
            fc1_b + i*MLPD, nullptr, nullptr, ml_hi, ml_lo, BNROWS, MLPD, DIMC);
        hmma_gemm<1><<<tc_grid(BNROWS, DIMC), 256, HM_SMEM>>>(
            ml_hi, ml_lo, f2_hi + (size_t)i*MLPD*DIMC, f2_lo + (size_t)i*MLPD*DIMC,
            fc2_b + i*DIMC, p_t, p_t, nullptr, nullptr, BNROWS, DIMC, MLPD);
    }

    ln_kernel<true><<<BNROWS, 256>>>(p_t, p_h, h_hi, h_lo, normf_g, normf_b);
    gather_cls_kernel<<<(BATCH*DIMC + 255)/256, 256>>>();
    sgemm_kernel<<<dim3((NCLS + 127)/128, 1), 256>>>(
        p_pooled, head_w, head_b, out, BATCH, NCLS, DIMC);
}

// round 10
// speedup vs baseline: 1.5003x; 1.5003x over previous
#include <cuda_runtime.h>
#include <cuda_bf16.h>
#include <math.h>
#include <stdint.h>

// ---------------- problem constants ----------------
#define DEPTH   12
#define DIMC    768
#define HEADS   12
#define MLPD    3072
#define NCLS    1000
#define NTOK    197
#define NPATCH  196
#define BATCH   32
#define HDIM    64
#define GRD     14
#define BNROWS  (BATCH*NTOK)     // 6304
#define PROWS   (BATCH*NPATCH)   // 6272
#define H3      (3*DIMC)         // 2304

// ---------------- scratch (fp32) ----------------
__device__ float g_pe[PROWS*DIMC];
__device__ float g_t[BNROWS*DIMC];
__device__ float g_h[BNROWS*DIMC];
__device__ float g_qkv[BNROWS*H3];
__device__ float g_pooled[BATCH*DIMC];

// ---------------- scratch (bf16 hi/lo activation planes) ----------------
__device__ __nv_bfloat16 g_px_hi[PROWS*DIMC],  g_px_lo[PROWS*DIMC];
__device__ __nv_bfloat16 g_h_hi[BNROWS*DIMC],  g_h_lo[BNROWS*DIMC];
__device__ __nv_bfloat16 g_ao_hi[BNROWS*DIMC], g_ao_lo[BNROWS*DIMC];
__device__ __nv_bfloat16 g_ml_hi[BNROWS*MLPD], g_ml_lo[BNROWS*MLPD];

// ---------------- scratch (bf16 hi/lo weight planes) ----------------
__device__ __nv_bfloat16 wpe_hi[DIMC*DIMC],       wpe_lo[DIMC*DIMC];
__device__ __nv_bfloat16 wqk_hi[DEPTH*DIMC*H3],   wqk_lo[DEPTH*DIMC*H3];
__device__ __nv_bfloat16 wpr_hi[DEPTH*DIMC*DIMC], wpr_lo[DEPTH*DIMC*DIMC];
__device__ __nv_bfloat16 wf1_hi[DEPTH*DIMC*MLPD], wf1_lo[DEPTH*DIMC*MLPD];
__device__ __nv_bfloat16 wf2_hi[DEPTH*MLPD*DIMC], wf2_lo[DEPTH*MLPD*DIMC];

// ---------------- helpers ----------------
__device__ __forceinline__ uint32_t smem_u32(const void* p) {
    uint32_t a;
    asm("{ .reg .u64 t; cvta.to.shared.u64 t, %1; cvt.u32.u64 %0, t; }"
        : "=r"(a) : "l"(p));
    return a;
}
__device__ __forceinline__ uint32_t pack2(__nv_bfloat16 a, __nv_bfloat16 b) {
    return (uint32_t)__bfloat16_as_ushort(a) |
           ((uint32_t)__bfloat16_as_ushort(b) << 16);
}
__device__ __forceinline__ void ldmx4(uint32_t* r, uint32_t addr) {
    asm volatile("ldmatrix.sync.aligned.m8n8.x4.shared.b16 {%0,%1,%2,%3}, [%4];"
        : "=r"(r[0]), "=r"(r[1]), "=r"(r[2]), "=r"(r[3]) : "r"(addr));
}
__device__ __forceinline__ void ldmx4t(uint32_t* r, uint32_t addr) {
    asm volatile("ldmatrix.sync.aligned.m8n8.x4.trans.shared.b16 {%0,%1,%2,%3}, [%4];"
        : "=r"(r[0]), "=r"(r[1]), "=r"(r[2]), "=r"(r[3]) : "r"(addr));
}
__device__ __forceinline__ void mma16816(float* d, const uint32_t* a, const uint32_t* b) {
    asm volatile(
        "mma.sync.aligned.m16n8k16.row.col.f32.bf16.bf16.f32 "
        "{%0,%1,%2,%3}, {%4,%5,%6,%7}, {%8,%9}, {%0,%1,%2,%3};"
        : "+f"(d[0]), "+f"(d[1]), "+f"(d[2]), "+f"(d[3])
        : "r"(a[0]), "r"(a[1]), "r"(a[2]), "r"(a[3]), "r"(b[0]), "r"(b[1]));
}
__device__ __forceinline__ void cpa16(uint32_t dst, const void* src, bool ok) {
    asm volatile("cp.async.cg.shared.global [%0], [%1], 16, %2;"
                 :: "r"(dst), "l"(src), "r"(ok ? 16 : 0) : "memory");
}

// ---------------- smem layout per stage (K-chunk = 64) ----------------
// Ahi/Alo: 128 rows x 72 bf16 (stride 144B) = 18432 B each
// Bhi/Blo: 64 rows x 136 bf16 (stride 272B) = 17408 B each
#define ASTR    72
#define BSTR    136
#define APLANE  18432
#define BOFF    36864
#define BPLANE  17408
#define BUFSZ   71680
#define NSTG    3
#define HM_SMEM (NSTG*BUFSZ)   // 215040 B -> 1 CTA/SM, deep pipeline

// ---------------- weight conversion: fp32 -> bf16 hi/lo ----------------
__global__ void convert_w(const float* __restrict__ src,
                          __nv_bfloat16* __restrict__ hi,
                          __nv_bfloat16* __restrict__ lo, int n4) {
    int i = blockIdx.x * blockDim.x + threadIdx.x;
    if (i >= n4) return;
    float4 v = *(const float4*)(src + i*4);
    __nv_bfloat16 h0=__float2bfloat16(v.x), h1=__float2bfloat16(v.y);
    __nv_bfloat16 h2=__float2bfloat16(v.z), h3=__float2bfloat16(v.w);
    *(uint32_t*)(hi + i*4)     = pack2(h0, h1);
    *(uint32_t*)(hi + i*4 + 2) = pack2(h2, h3);
    *(uint32_t*)(lo + i*4)     = pack2(__float2bfloat16(v.x-__bfloat162float(h0)),
                                       __float2bfloat16(v.y-__bfloat162float(h1)));
    *(uint32_t*)(lo + i*4 + 2) = pack2(__float2bfloat16(v.z-__bfloat162float(h2)),
                                       __float2bfloat16(v.w-__bfloat162float(h3)));
}

// ============ bf16 3-split mma.sync GEMM (K-chunk 64, 3-stage) ============
// EPI: 0=bias->f32, 1=bias+residual->f32, 2=bias+GELU->bf16 hi/lo planes
template<int EPI>
__global__ __launch_bounds__(256) void hmma_gemm(
    const __nv_bfloat16* __restrict__ Ahi, const __nv_bfloat16* __restrict__ Alo,
    const __nv_bfloat16* __restrict__ Whi, const __nv_bfloat16* __restrict__ Wlo,
    const float* __restrict__ bias, const float* __restrict__ Res,
    float* __restrict__ C,
    __nv_bfloat16* __restrict__ Chi, __nv_bfloat16* __restrict__ Clo,
    int M, int N, int K)
{
    extern __shared__ char smem[];
    const uint32_t sb = smem_u32(smem);
    const int tid  = threadIdx.x;
    const int warp = tid >> 5;
    const int lane = tid & 31;
    const int mbase = blockIdx.y * 128;
    const int nbase = blockIdx.x * 128;

    const int wm = (warp & 1) * 64;
    const int wn = (warp >> 1) * 32;

    float d[4][4][4];
    #pragma unroll
    for (int i = 0; i < 4; i++)
        #pragma unroll
        for (int j = 0; j < 4; j++)
            #pragma unroll
            for (int r = 0; r < 4; r++) d[i][j][r] = 0.f;

    const int nch = K >> 6;   // K/64

    // A: 2 planes x 128 rows x 8 segs = 2048 segs; B: 2 x 64 x 16 = 2048
    #define ISSUE(c, bsel) do {                                               \
        const uint32_t dbase = sb + (uint32_t)(bsel) * BUFSZ;                 \
        const int k0 = (c) << 6;                                              \
        _Pragma("unroll")                                                     \
        for (int i = 0; i < 8; i++) {                                         \
            int t = tid + i*256;                                              \
            int p = t >> 10, idx = t & 1023;                                  \
            int row = idx >> 3, seg = idx & 7;                                \
            bool ok = (mbase + row) < M;                                      \
            const __nv_bfloat16* sp = (p ? Alo : Ahi);                        \
            const __nv_bfloat16* src = ok ? sp + (size_t)(mbase+row)*K + k0 + seg*8 : sp; \
            cpa16(dbase + (uint32_t)(p*APLANE + row*144 + seg*16), src, ok);  \
        }                                                                     \
        _Pragma("unroll")                                                     \
        for (int i = 0; i < 8; i++) {                                         \
            int t = tid + i*256;                                              \
            int p = t >> 10, idx = t & 1023;                                  \
            int row = idx >> 4, seg = idx & 15;                               \
            const __nv_bfloat16* src = (p ? Wlo : Whi) + (size_t)(k0+row)*N + nbase + seg*8; \
            cpa16(dbase + (uint32_t)(BOFF + p*BPLANE + row*272 + seg*16), src, true); \
        }                                                                     \
        asm volatile("cp.async.commit_group;" ::: "memory");                  \
    } while (0)

    ISSUE(0, 0);
    ISSUE(1, 1);

    int bsel = 0, bnext = 2;
    for (int c = 0; c < nch; ++c) {
        if (c + 2 < nch) {
            ISSUE(c + 2, bnext);
            asm volatile("cp.async.wait_group 2;" ::: "memory");
        } else if (c + 1 < nch) {
            asm volatile("cp.async.wait_group 1;" ::: "memory");
        } else {
            asm volatile("cp.async.wait_group 0;" ::: "memory");
        }
        __syncthreads();

        const uint32_t sbuf = sb + (uint32_t)bsel * BUFSZ;
        bnext = bsel;
        bsel = (bsel + 1 == NSTG) ? 0 : bsel + 1;

        #pragma unroll
        for (int ks = 0; ks < 4; ++ks) {
            const uint32_t aoff = sbuf +
                (uint32_t)((wm + (lane & 15))*ASTR + ks*16 + (lane >> 4)*8) * 2;
            const uint32_t boff = sbuf + BOFF +
                (uint32_t)((ks*16 + (lane & 15))*BSTR + wn + (lane >> 4)*8) * 2;

            uint32_t ahi[4][4], bhi[4][2];
            #pragma unroll
            for (int mt = 0; mt < 4; mt++) ldmx4(ahi[mt], aoff + mt*(16*ASTR*2));
            #pragma unroll
            for (int ng = 0; ng < 2; ng++) {
                uint32_t r[4];
                ldmx4t(r, boff + ng*32);
                bhi[2*ng][0]   = r[0]; bhi[2*ng][1]   = r[1];
                bhi[2*ng+1][0] = r[2]; bhi[2*ng+1][1] = r[3];
            }
            #pragma unroll
            for (int mt = 0; mt < 4; mt++)
                #pragma unroll
                for (int nt = 0; nt < 4; nt++)
                    mma16816(d[mt][nt], ahi[mt], bhi[nt]);

            {
                uint32_t blo[4][2];
                #pragma unroll
                for (int ng = 0; ng < 2; ng++) {
                    uint32_t r[4];
                    ldmx4t(r, boff + BPLANE + ng*32);
                    blo[2*ng][0]   = r[0]; blo[2*ng][1]   = r[1];
                    blo[2*ng+1][0] = r[2]; blo[2*ng+1][1] = r[3];
                }
                #pragma unroll
                for (int mt = 0; mt < 4; mt++)
                    #pragma unroll
                    for (int nt = 0; nt < 4; nt++)
                        mma16816(d[mt][nt], ahi[mt], blo[nt]);
            }
            {
                uint32_t alo[4][4];
                #pragma unroll
                for (int mt = 0; mt < 4; mt++)
                    ldmx4(alo[mt], aoff + APLANE + mt*(16*ASTR*2));
                #pragma unroll
                for (int mt = 0; mt < 4; mt++)
                    #pragma unroll
                    for (int nt = 0; nt < 4; nt++)
                        mma16816(d[mt][nt], alo[mt], bhi[nt]);
            }
        }
        __syncthreads();
    }
    #undef ISSUE

    // ---- epilogue ----
    #pragma unroll
    for (int mt = 0; mt < 4; mt++) {
        const int r0 = mbase + wm + mt*16 + (lane >> 2);
        #pragma unroll
        for (int nt = 0; nt < 4; nt++) {
            const int c0 = nbase + wn + nt*8 + (lane & 3)*2;
            const float b0 = bias[c0], b1 = bias[c0+1];
            #pragma unroll
            for (int half = 0; half < 2; half++) {
                const int row = r0 + half*8;
                if (row >= M) continue;
                float v0 = d[mt][nt][2*half+0] + b0;
                float v1 = d[mt][nt][2*half+1] + b1;
                if (EPI == 1) {
                    const float* rr = Res + (size_t)row * N + c0;
                    v0 += rr[0]; v1 += rr[1];
                }
                if (EPI == 2) {
                    v0 = 0.5f*v0*(1.f + erff(v0*0.70710678118654752f));
                    v1 = 0.5f*v1*(1.f + erff(v1*0.70710678118654752f));
                    __nv_bfloat16 h0 = __float2bfloat16(v0);
                    __nv_bfloat16 h1 = __float2bfloat16(v1);
                    *(uint32_t*)(Chi + (size_t)row * N + c0) = pack2(h0, h1);
                    *(uint32_t*)(Clo + (size_t)row * N + c0) =
                        pack2(__float2bfloat16(v0 - __bfloat162float(h0)),
                              __float2bfloat16(v1 - __bfloat162float(h1)));
                } else {
                    *(float2*)(C + (size_t)row * N + c0) = make_float2(v0, v1);
                }
            }
        }
    }
}

// ---------------- patch extraction -> bf16 hi/lo ----------------
__global__ void patchify_kernel(const float* __restrict__ x) {
    int idx = blockIdx.x * blockDim.x + threadIdx.x;
    if (idx >= PROWS * DIMC) return;
    int col = idx % DIMC;
    int row = idx / DIMC;
    int b   = row / NPATCH;
    int n   = row % NPATCH;
    int g1  = n / GRD, g2 = n % GRD;
    int c   = col >> 8;
    int p1  = (col >> 4) & 15;
    int p2  = col & 15;
    float v = x[((b*3 + c)*224 + g1*16 + p1)*224 + g2*16 + p2];
    __nv_bfloat16 h = __float2bfloat16(v);
    g_px_hi[idx] = h;
    g_px_lo[idx] = __float2bfloat16(v - __bfloat162float(h));
}

// ---------------- cls concat + pos embed ----------------
__global__ void embed_kernel(const float* __restrict__ cls,
                             const float* __restrict__ pos) {
    int idx = blockIdx.x * blockDim.x + threadIdx.x;
    if (idx >= BNROWS * DIMC) return;
    int d = idx % DIMC;
    int r = idx / DIMC;
    int b = r / NTOK;
    int n = r % NTOK;
    float v = (n == 0) ? cls[d] : g_pe[(b*NPATCH + n - 1)*DIMC + d];
    g_t[idx] = v + pos[n*DIMC + d];
}

// ---------------- layernorm -> bf16 hi/lo (+ optional fp32) ----------------
template<bool WF32>
__global__ __launch_bounds__(256) void ln_kernel(const float* __restrict__ in,
                                                 float* __restrict__ out,
                                                 __nv_bfloat16* __restrict__ ohi,
                                                 __nv_bfloat16* __restrict__ olo,
                                                 const float* __restrict__ gam,
                                                 const float* __restrict__ bet) {
    int row = blockIdx.x;
    const float* x = in + row*DIMC;
    float vals[3];
    float s = 0.f, s2 = 0.f;
    #pragma unroll
    for (int i = 0; i < 3; i++) {
        float v = x[threadIdx.x + i*256];
        vals[i] = v; s += v; s2 += v*v;
    }
    #pragma unroll
    for (int o = 16; o; o >>= 1) {
        s  += __shfl_xor_sync(0xffffffffu, s,  o);
        s2 += __shfl_xor_sync(0xffffffffu, s2, o);
    }
    __shared__ float red[18];
    int wid = threadIdx.x >> 5, lane = threadIdx.x & 31;
    if (lane == 0) { red[wid] = s; red[wid + 8] = s2; }
    __syncthreads();
    if (threadIdx.x < 32) {
        float a  = (lane < 8) ? red[lane]     : 0.f;
        float b2 = (lane < 8) ? red[lane + 8] : 0.f;
        #pragma unroll
        for (int o = 4; o; o >>= 1) {
            a  += __shfl_xor_sync(0xffffffffu, a,  o);
            b2 += __shfl_xor_sync(0xffffffffu, b2, o);
        }
        if (lane == 0) { red[16] = a; red[17] = b2; }
    }
    __syncthreads();
    float mean = red[16] * (1.f/768.f);
    float var  = red[17] * (1.f/768.f) - mean*mean;
    float inv  = rsqrtf(var + 1e-6f);
    #pragma unroll
    for (int i = 0; i < 3; i++) {
        int c = threadIdx.x + i*256;
        float v = (vals[i] - mean) * inv * gam[c] + bet[c];
        if (WF32) out[row*DIMC + c] = v;
        __nv_bfloat16 h = __float2bfloat16(v);
        ohi[row*DIMC + c] = h;
        olo[row*DIMC + c] = __float2bfloat16(v - __bfloat162float(h));
    }
}

// ---------------- SIMT sgemm (head only, M=32) ----------------
__global__ __launch_bounds__(256) void sgemm_kernel(
    const float* __restrict__ A, const float* __restrict__ B,
    const float* __restrict__ bias,
    float* __restrict__ C, int M, int N, int K)
{
    __shared__ float As[8][128];
    __shared__ float Bs[8][128];
    int tid = threadIdx.x;
    int bx = blockIdx.x, by = blockIdx.y;
    int tr = tid >> 4;
    int tc = tid & 15;

    float acc[8][8];
    #pragma unroll
    for (int i = 0; i < 8; i++)
        #pragma unroll
        for (int j = 0; j < 8; j++) acc[i][j] = 0.f;

    int aRow = tid >> 1;
    int aCol = (tid & 1) * 4;
    int bRow = tid >> 5;
    int bCol = (tid & 31) * 4;
    int gARow = by*128 + aRow;
    int gBCol = bx*128 + bCol;
    const float* Aptr = A + gARow*K + aCol;
    const float* Bptr = B + bRow*N + gBCol;
    bool aValid = (gARow < M);
    bool bValid = (gBCol < N);

    for (int k0 = 0; k0 < K; k0 += 8) {
        float4 av = aValid ? *(const float4*)(Aptr + k0)
                           : make_float4(0.f,0.f,0.f,0.f);
        float4 bv = bValid ? *(const float4*)(Bptr + k0*N)
                           : make_float4(0.f,0.f,0.f,0.f);
        As[aCol+0][aRow] = av.x;
        As[aCol+1][aRow] = av.y;
        As[aCol+2][aRow] = av.z;
        As[aCol+3][aRow] = av.w;
        *(float4*)&Bs[bRow][bCol] = bv;
        __syncthreads();
        #pragma unroll
        for (int kk = 0; kk < 8; kk++) {
            float a[8], b[8];
            #pragma unroll
            for (int i = 0; i < 8; i++) a[i] = As[kk][tr*8 + i];
            #pragma unroll
            for (int j = 0; j < 8; j++) b[j] = Bs[kk][tc*8 + j];
            #pragma unroll
            for (int i = 0; i < 8; i++)
                #pragma unroll
                for (int j = 0; j < 8; j++)
                    acc[i][j] += a[i] * b[j];
        }
        __syncthreads();
    }

    #pragma unroll
    for (int i = 0; i < 8; i++) {
        int row = by*128 + tr*8 + i;
        if (row >= M) continue;
        #pragma unroll
        for (int j = 0; j < 8; j++) {
            int col = bx*128 + tc*8 + j;
            if (col >= N) continue;
            C[row*N + col] = acc[i][j] + bias[col];
        }
    }
}

// ---------------- attention (optimized SIMT) ----------------
#define KTSTR 202
#define ATTN_F (64*KTSTR + NTOK*64 + 8*200 + 8*64)
#define ATTN_SMEM (ATTN_F*4)

__global__ __launch_bounds__(256, 2) void attention_kernel(const float* __restrict__ mask) {
    extern __shared__ float sm[];
    float* Kt = sm;                    // 64 x KTSTR
    float* Vs = Kt + 64*KTSTR;         // 197 rows x 64 floats (float2-paired)
    float* Ps = Vs + NTOK*64;          // 8 x 200
    float* Qs = Ps + 8*200;            // 8 x 64

    int bh = blockIdx.x;
    int b = bh / HEADS, h = bh % HEADS;
    int tid = threadIdx.x, warp = tid >> 5, lane = tid & 31;
    const float scale = 0.125f;
    int base = (b*NTOK)*H3 + h*HDIM;

    for (int idx = tid; idx < NTOK*HDIM; idx += 256) {
        int j = idx >> 6, d = idx & 63;
        Kt[d*KTSTR + j] = g_qkv[base + j*H3 + DIMC + d];
        Vs[j*64 + (d & 31)*2 + (d >> 5)] = g_qkv[base + j*H3 + 2*DIMC + d];
    }
    __syncthreads();

    for (int r = warp; r < NTOK; r += 8) {
        Qs[warp*64 + lane]      = g_qkv[base + r*H3 + lane];
        Qs[warp*64 + lane + 32] = g_qkv[base + r*H3 + lane + 32];
        __syncwarp();
        float q[64];
        #pragma unroll
        for (int d = 0; d < 64; d++) q[d] = Qs[warp*64 + d];

        float2 sp[4];
        float mx = -1e30f;
        #pragma unroll
        for (int jj = 0; jj < 4; jj++) {
            int j0 = jj*64 + 2*lane;
            bool v0 = j0 < NTOK, v1 = (j0 + 1) < NTOK;
            float s0 = -1e30f, s1 = -1e30f;
            if (v0) {
                float a0 = 0.f, a1 = 0.f;
                #pragma unroll
                for (int d = 0; d < 64; d++) {
                    float2 kk = *(const float2*)(Kt + d*KTSTR + j0);
                    a0 += q[d] * kk.x;
                    a1 += q[d] * kk.y;
                }
                s0 = a0 * scale * mask[r*NTOK + j0];
                mx = fmaxf(mx, s0);
                if (v1) {
                    s1 = a1 * scale * mask[r*NTOK + j0 + 1];
                    mx = fmaxf(mx, s1);
                }
            }
            sp[jj] = make_float2(s0, s1);
        }
        #pragma unroll
        for (int o = 16; o; o >>= 1)
            mx = fmaxf(mx, __shfl_xor_sync(0xffffffffu, mx, o));

        float sum = 0.f;
        #pragma unroll
        for (int jj = 0; jj < 4; jj++) {
            float p0 = expf(sp[jj].x - mx);
            float p1 = expf(sp[jj].y - mx);
            sp[jj] = make_float2(p0, p1);
            sum += p0 + p1;
        }
        #pragma unroll
        for (int o = 16; o; o >>= 1)
            sum += __shfl_xor_sync(0xffffffffu, sum, o);
        float rinv = 1.f / sum;

        #pragma unroll
        for (int jj = 0; jj < 4; jj++) {
            int j0 = jj*64 + 2*lane;
            if (j0 < NTOK)     Ps[warp*200 + j0]     = sp[jj].x * rinv;
            if (j0 + 1 < NTOK) Ps[warp*200 + j0 + 1] = sp[jj].y * rinv;
        }
        __syncwarp();

        float o0 = 0.f, o1 = 0.f;
        #pragma unroll 4
        for (int j = 0; j < NTOK; j++) {
            float p = Ps[warp*200 + j];
            float2 vv = *(const float2*)(Vs + j*64 + 2*lane);
            o0 += p * vv.x;
            o1 += p * vv.y;
        }
        int orow = (b*NTOK + r)*DIMC + h*HDIM;
        __nv_bfloat16 h0 = __float2bfloat16(o0);
        __nv_bfloat16 h1 = __float2bfloat16(o1);
        g_ao_hi[orow + lane]      = h0;
        g_ao_hi[orow + lane + 32] = h1;
        g_ao_lo[orow + lane]      = __float2bfloat16(o0 - __bfloat162float(h0));
        g_ao_lo[orow + lane + 32] = __float2bfloat16(o1 - __bfloat162float(h1));
    }
}

// ---------------- gather cls rows ----------------
__global__ void gather_cls_kernel() {
    int idx = blockIdx.x * blockDim.x + threadIdx.x;
    if (idx >= BATCH * DIMC) return;
    int b = idx / DIMC, d = idx % DIMC;
    g_pooled[idx] = g_h[(b*NTOK)*DIMC + d];
}

// ---------------- host driver ----------------
static inline dim3 tc_grid(int M, int N) {
    return dim3(N / 128, (M + 127) / 128);
}

#define SYMADDR(var, sym) cudaGetSymbolAddress((void**)&var, sym)

extern "C" void kernel_launch(void* const* d_in, const int* in_sizes, int n_in,
                              void* d_out, int out_size) {
    (void)in_sizes; (void)n_in; (void)out_size;
    const float* x       = (const float*)d_in[0];
    const float* cp_mask = (const float*)d_in[1];
    const float* patch_w = (const float*)d_in[2];
    const float* patch_b = (const float*)d_in[3];
    const float* cls     = (const float*)d_in[4];
    const float* pos     = (const float*)d_in[5];
    const float* ln1_g   = (const float*)d_in[6];
    const float* ln1_b   = (const float*)d_in[7];
    const float* qkv_w   = (const float*)d_in[8];
    const float* qkv_b   = (const float*)d_in[9];
    const float* proj_w  = (const float*)d_in[10];
    const float* proj_b  = (const float*)d_in[11];
    const float* ln2_g   = (const float*)d_in[12];
    const float* ln2_b   = (const float*)d_in[13];
    const float* fc1_w   = (const float*)d_in[14];
    const float* fc1_b   = (const float*)d_in[15];
    const float* fc2_w   = (const float*)d_in[16];
    const float* fc2_b   = (const float*)d_in[17];
    const float* normf_g = (const float*)d_in[18];
    const float* normf_b = (const float*)d_in[19];
    const float* head_w  = (const float*)d_in[20];
    const float* head_b  = (const float*)d_in[21];
    float* out = (float*)d_out;

    float *p_pe, *p_t, *p_h, *p_qkv, *p_pooled;
    SYMADDR(p_pe, g_pe); SYMADDR(p_t, g_t); SYMADDR(p_h, g_h);
    SYMADDR(p_qkv, g_qkv); SYMADDR(p_pooled, g_pooled);

    __nv_bfloat16 *px_hi, *px_lo, *h_hi, *h_lo, *ao_hi, *ao_lo, *ml_hi, *ml_lo;
    SYMADDR(px_hi, g_px_hi); SYMADDR(px_lo, g_px_lo);
    SYMADDR(h_hi, g_h_hi);   SYMADDR(h_lo, g_h_lo);
    SYMADDR(ao_hi, g_ao_hi); SYMADDR(ao_lo, g_ao_lo);
    SYMADDR(ml_hi, g_ml_hi); SYMADDR(ml_lo, g_ml_lo);

    __nv_bfloat16 *pe_hi, *pe_lo, *qk_hi, *qk_lo, *pr_hi, *pr_lo,
                  *f1_hi, *f1_lo, *f2_hi, *f2_lo;
    SYMADDR(pe_hi, wpe_hi); SYMADDR(pe_lo, wpe_lo);
    SYMADDR(qk_hi, wqk_hi); SYMADDR(qk_lo, wqk_lo);
    SYMADDR(pr_hi, wpr_hi); SYMADDR(pr_lo, wpr_lo);
    SYMADDR(f1_hi, wf1_hi); SYMADDR(f1_lo, wf1_lo);
    SYMADDR(f2_hi, wf2_hi); SYMADDR(f2_lo, wf2_lo);

    cudaFuncSetAttribute(attention_kernel,
                         cudaFuncAttributeMaxDynamicSharedMemorySize, (int)ATTN_SMEM);
    cudaFuncSetAttribute(hmma_gemm<0>,
                         cudaFuncAttributeMaxDynamicSharedMemorySize, HM_SMEM);
    cudaFuncSetAttribute(hmma_gemm<1>,
                         cudaFuncAttributeMaxDynamicSharedMemorySize, HM_SMEM);
    cudaFuncSetAttribute(hmma_gemm<2>,
                         cudaFuncAttributeMaxDynamicSharedMemorySize, HM_SMEM);

    // ---- weight pre-conversion (bulk, once per launch) ----
    {
        int n4;
        n4 = (DIMC*DIMC)/4;
        convert_w<<<(n4+255)/256, 256>>>(patch_w, pe_hi, pe_lo, n4);
        n4 = (DEPTH*DIMC*H3)/4;
        convert_w<<<(n4+255)/256, 256>>>(qkv_w, qk_hi, qk_lo, n4);
        n4 = (DEPTH*DIMC*DIMC)/4;
        convert_w<<<(n4+255)/256, 256>>>(proj_w, pr_hi, pr_lo, n4);
        n4 = (DEPTH*DIMC*MLPD)/4;
        convert_w<<<(n4+255)/256, 256>>>(fc1_w, f1_hi, f1_lo, n4);
        n4 = (DEPTH*MLPD*DIMC)/4;
        convert_w<<<(n4+255)/256, 256>>>(fc2_w, f2_hi, f2_lo, n4);
    }

    patchify_kernel<<<(PROWS*DIMC + 255)/256, 256>>>(x);
    hmma_gemm<0><<<tc_grid(PROWS, DIMC), 256, HM_SMEM>>>(
        px_hi, px_lo, pe_hi, pe_lo, patch_b, nullptr,
        p_pe, nullptr, nullptr, PROWS, DIMC, DIMC);
    embed_kernel<<<(BNROWS*DIMC + 255)/256, 256>>>(cls, pos);

    for (int i = 0; i < DEPTH; i++) {
        ln_kernel<false><<<BNROWS, 256>>>(p_t, nullptr, h_hi, h_lo,
                                          ln1_g + i*DIMC, ln1_b + i*DIMC);
        hmma_gemm<0><<<tc_grid(BNROWS, H3), 256, HM_SMEM>>>(
            h_hi, h_lo, qk_hi + (size_t)i*DIMC*H3, qk_lo + (size_t)i*DIMC*H3,
            qkv_b + i*H3, nullptr, p_qkv, nullptr, nullptr, BNROWS, H3, DIMC);
        attention_kernel<<<BATCH*HEADS, 256, ATTN_SMEM>>>(cp_mask);
        hmma_gemm<1><<<tc_grid(BNROWS, DIMC), 256, HM_SMEM>>>(
            ao_hi, ao_lo, pr_hi + (size_t)i*DIMC*DIMC, pr_lo + (size_t)i*DIMC*DIMC,
            proj_b + i*DIMC, p_t, p_t, nullptr, nullptr, BNROWS, DIMC, DIMC);
        ln_kernel<false><<<BNROWS, 256>>>(p_t, nullptr, h_hi, h_lo,
                                          ln2_g + i*DIMC, ln2_b + i*DIMC);
        hmma_gemm<2><<<tc_grid(BNROWS, MLPD), 256, HM_SMEM>>>(
            h_hi, h_lo, f1_hi + (size_t)i*DIMC*MLPD, f1_lo + (size_t)i*DIMC*MLPD,
            fc1_b + i*MLPD, nullptr, nullptr, ml_hi, ml_lo, BNROWS, MLPD, DIMC);
        hmma_gemm<1><<<tc_grid(BNROWS, DIMC), 256, HM_SMEM>>>(
            ml_hi, ml_lo, f2_hi + (size_t)i*MLPD*DIMC, f2_lo + (size_t)i*MLPD*DIMC,
            fc2_b + i*DIMC, p_t, p_t, nullptr, nullptr, BNROWS, DIMC, MLPD);
    }

    ln_kernel<true><<<BNROWS, 256>>>(p_t, p_h, h_hi, h_lo, normf_g, normf_b);
    gather_cls_kernel<<<(BATCH*DIMC + 255)/256, 256>>>();
    sgemm_kernel<<<dim3((NCLS + 127)/128, 1), 256>>>(
        p_pooled, head_w, head_b, out, BATCH, NCLS, DIMC);
}

// round 12
// speedup vs baseline: 1.5003x; 1.0000x over previous
#include <cuda_runtime.h>
#include <cuda_bf16.h>
#include <math.h>
#include <stdint.h>

// ---------------- problem constants ----------------
#define DEPTH   12
#define DIMC    768
#define HEADS   12
#define MLPD    3072
#define NCLS    1000
#define NTOK    197
#define NPATCH  196
#define BATCH   32
#define HDIM    64
#define GRD     14
#define BNROWS  (BATCH*NTOK)     // 6304
#define PROWS   (BATCH*NPATCH)   // 6272
#define H3      (3*DIMC)         // 2304

// ---------------- scratch (fp32) ----------------
__device__ float g_pe[PROWS*DIMC];
__device__ float g_t[BNROWS*DIMC];
__device__ float g_h[BNROWS*DIMC];
__device__ float g_qkv[BNROWS*H3];
__device__ float g_pooled[BATCH*DIMC];

// ---------------- scratch (bf16 hi/lo activation planes) ----------------
__device__ __nv_bfloat16 g_px_hi[PROWS*DIMC],  g_px_lo[PROWS*DIMC];
__device__ __nv_bfloat16 g_h_hi[BNROWS*DIMC],  g_h_lo[BNROWS*DIMC];
__device__ __nv_bfloat16 g_ao_hi[BNROWS*DIMC], g_ao_lo[BNROWS*DIMC];
__device__ __nv_bfloat16 g_ml_hi[BNROWS*MLPD], g_ml_lo[BNROWS*MLPD];

// ---------------- scratch (bf16 hi/lo weight planes) ----------------
__device__ __nv_bfloat16 wpe_hi[DIMC*DIMC],       wpe_lo[DIMC*DIMC];
__device__ __nv_bfloat16 wqk_hi[DEPTH*DIMC*H3],   wqk_lo[DEPTH*DIMC*H3];
__device__ __nv_bfloat16 wpr_hi[DEPTH*DIMC*DIMC], wpr_lo[DEPTH*DIMC*DIMC];
__device__ __nv_bfloat16 wf1_hi[DEPTH*DIMC*MLPD], wf1_lo[DEPTH*DIMC*MLPD];
__device__ __nv_bfloat16 wf2_hi[DEPTH*MLPD*DIMC], wf2_lo[DEPTH*MLPD*DIMC];

// ---------------- helpers ----------------
__device__ __forceinline__ uint32_t smem_u32(const void* p) {
    uint32_t a;
    asm("{ .reg .u64 t; cvta.to.shared.u64 t, %1; cvt.u32.u64 %0, t; }"
        : "=r"(a) : "l"(p));
    return a;
}
__device__ __forceinline__ uint32_t pack2(__nv_bfloat16 a, __nv_bfloat16 b) {
    return (uint32_t)__bfloat16_as_ushort(a) |
           ((uint32_t)__bfloat16_as_ushort(b) << 16);
}
__device__ __forceinline__ void ldmx4(uint32_t* r, uint32_t addr) {
    asm volatile("ldmatrix.sync.aligned.m8n8.x4.shared.b16 {%0,%1,%2,%3}, [%4];"
        : "=r"(r[0]), "=r"(r[1]), "=r"(r[2]), "=r"(r[3]) : "r"(addr));
}
__device__ __forceinline__ void ldmx4t(uint32_t* r, uint32_t addr) {
    asm volatile("ldmatrix.sync.aligned.m8n8.x4.trans.shared.b16 {%0,%1,%2,%3}, [%4];"
        : "=r"(r[0]), "=r"(r[1]), "=r"(r[2]), "=r"(r[3]) : "r"(addr));
}
__device__ __forceinline__ void mma16816(float* d, const uint32_t* a, const uint32_t* b) {
    asm volatile(
        "mma.sync.aligned.m16n8k16.row.col.f32.bf16.bf16.f32 "
        "{%0,%1,%2,%3}, {%4,%5,%6,%7}, {%8,%9}, {%0,%1,%2,%3};"
        : "+f"(d[0]), "+f"(d[1]), "+f"(d[2]), "+f"(d[3])
        : "r"(a[0]), "r"(a[1]), "r"(a[2]), "r"(a[3]), "r"(b[0]), "r"(b[1]));
}
__device__ __forceinline__ void cpa16(uint32_t dst, const void* src, bool ok) {
    asm volatile("cp.async.cg.shared.global [%0], [%1], 16, %2;"
                 :: "r"(dst), "l"(src), "r"(ok ? 16 : 0) : "memory");
}

// ---------------- smem layout per stage (K-chunk = 64) ----------------
// Ahi/Alo: 128 rows x 72 bf16 (stride 144B) = 18432 B each
// Bhi/Blo: 64 rows x 136 bf16 (stride 272B) = 17408 B each
#define ASTR    72
#define BSTR    136
#define APLANE  18432
#define BOFF    36864
#define BPLANE  17408
#define BUFSZ   71680
#define NSTG    3
#define HM_SMEM (NSTG*BUFSZ)   // 215040 B -> 1 CTA/SM, deep pipeline

// ---------------- weight conversion: fp32 -> bf16 hi/lo ----------------
__global__ void convert_w(const float* __restrict__ src,
                          __nv_bfloat16* __restrict__ hi,
                          __nv_bfloat16* __restrict__ lo, int n4) {
    int i = blockIdx.x * blockDim.x + threadIdx.x;
    if (i >= n4) return;
    float4 v = *(const float4*)(src + i*4);
    __nv_bfloat16 h0=__float2bfloat16(v.x), h1=__float2bfloat16(v.y);
    __nv_bfloat16 h2=__float2bfloat16(v.z), h3=__float2bfloat16(v.w);
    *(uint32_t*)(hi + i*4)     = pack2(h0, h1);
    *(uint32_t*)(hi + i*4 + 2) = pack2(h2, h3);
    *(uint32_t*)(lo + i*4)     = pack2(__float2bfloat16(v.x-__bfloat162float(h0)),
                                       __float2bfloat16(v.y-__bfloat162float(h1)));
    *(uint32_t*)(lo + i*4 + 2) = pack2(__float2bfloat16(v.z-__bfloat162float(h2)),
                                       __float2bfloat16(v.w-__bfloat162float(h3)));
}

// ============ bf16 3-split mma.sync GEMM (K-chunk 64, 3-stage) ============
// EPI: 0=bias->f32, 1=bias+residual->f32, 2=bias+GELU->bf16 hi/lo planes
template<int EPI>
__global__ __launch_bounds__(256) void hmma_gemm(
    const __nv_bfloat16* __restrict__ Ahi, const __nv_bfloat16* __restrict__ Alo,
    const __nv_bfloat16* __restrict__ Whi, const __nv_bfloat16* __restrict__ Wlo,
    const float* __restrict__ bias, const float* __restrict__ Res,
    float* __restrict__ C,
    __nv_bfloat16* __restrict__ Chi, __nv_bfloat16* __restrict__ Clo,
    int M, int N, int K)
{
    extern __shared__ char smem[];
    const uint32_t sb = smem_u32(smem);
    const int tid  = threadIdx.x;
    const int warp = tid >> 5;
    const int lane = tid & 31;
    const int mbase = blockIdx.y * 128;
    const int nbase = blockIdx.x * 128;

    const int wm = (warp & 1) * 64;
    const int wn = (warp >> 1) * 32;

    float d[4][4][4];
    #pragma unroll
    for (int i = 0; i < 4; i++)
        #pragma unroll
        for (int j = 0; j < 4; j++)
            #pragma unroll
            for (int r = 0; r < 4; r++) d[i][j][r] = 0.f;

    const int nch = K >> 6;   // K/64

    // A: 2 planes x 128 rows x 8 segs = 2048 segs; B: 2 x 64 x 16 = 2048
    #define ISSUE(c, bsel) do {                                               \
        const uint32_t dbase = sb + (uint32_t)(bsel) * BUFSZ;                 \
        const int k0 = (c) << 6;                                              \
        _Pragma("unroll")                                                     \
        for (int i = 0; i < 8; i++) {                                         \
            int t = tid + i*256;                                              \
            int p = t >> 10, idx = t & 1023;                                  \
            int row = idx >> 3, seg = idx & 7;                                \
            bool ok = (mbase + row) < M;                                      \
            const __nv_bfloat16* sp = (p ? Alo : Ahi);                        \
            const __nv_bfloat16* src = ok ? sp + (size_t)(mbase+row)*K + k0 + seg*8 : sp; \
            cpa16(dbase + (uint32_t)(p*APLANE + row*144 + seg*16), src, ok);  \
        }                                                                     \
        _Pragma("unroll")                                                     \
        for (int i = 0; i < 8; i++) {                                         \
            int t = tid + i*256;                                              \
            int p = t >> 10, idx = t & 1023;                                  \
            int row = idx >> 4, seg = idx & 15;                               \
            const __nv_bfloat16* src = (p ? Wlo : Whi) + (size_t)(k0+row)*N + nbase + seg*8; \
            cpa16(dbase + (uint32_t)(BOFF + p*BPLANE + row*272 + seg*16), src, true); \
        }                                                                     \
        asm volatile("cp.async.commit_group;" ::: "memory");                  \
    } while (0)

    ISSUE(0, 0);
    ISSUE(1, 1);

    int bsel = 0, bnext = 2;
    for (int c = 0; c < nch; ++c) {
        if (c + 2 < nch) {
            ISSUE(c + 2, bnext);
            asm volatile("cp.async.wait_group 2;" ::: "memory");
        } else if (c + 1 < nch) {
            asm volatile("cp.async.wait_group 1;" ::: "memory");
        } else {
            asm volatile("cp.async.wait_group 0;" ::: "memory");
        }
        __syncthreads();

        const uint32_t sbuf = sb + (uint32_t)bsel * BUFSZ;
        bnext = bsel;
        bsel = (bsel + 1 == NSTG) ? 0 : bsel + 1;

        #pragma unroll
        for (int ks = 0; ks < 4; ++ks) {
            const uint32_t aoff = sbuf +
                (uint32_t)((wm + (lane & 15))*ASTR + ks*16 + (lane >> 4)*8) * 2;
            const uint32_t boff = sbuf + BOFF +
                (uint32_t)((ks*16 + (lane & 15))*BSTR + wn + (lane >> 4)*8) * 2;

            uint32_t ahi[4][4], bhi[4][2];
            #pragma unroll
            for (int mt = 0; mt < 4; mt++) ldmx4(ahi[mt], aoff + mt*(16*ASTR*2));
            #pragma unroll
            for (int ng = 0; ng < 2; ng++) {
                uint32_t r[4];
                ldmx4t(r, boff + ng*32);
                bhi[2*ng][0]   = r[0]; bhi[2*ng][1]   = r[1];
                bhi[2*ng+1][0] = r[2]; bhi[2*ng+1][1] = r[3];
            }
            #pragma unroll
            for (int mt = 0; mt < 4; mt++)
                #pragma unroll
                for (int nt = 0; nt < 4; nt++)
                    mma16816(d[mt][nt], ahi[mt], bhi[nt]);

            {
                uint32_t blo[4][2];
                #pragma unroll
                for (int ng = 0; ng < 2; ng++) {
                    uint32_t r[4];
                    ldmx4t(r, boff + BPLANE + ng*32);
                    blo[2*ng][0]   = r[0]; blo[2*ng][1]   = r[1];
                    blo[2*ng+1][0] = r[2]; blo[2*ng+1][1] = r[3];
                }
                #pragma unroll
                for (int mt = 0; mt < 4; mt++)
                    #pragma unroll
                    for (int nt = 0; nt < 4; nt++)
                        mma16816(d[mt][nt], ahi[mt], blo[nt]);
            }
            {
                uint32_t alo[4][4];
                #pragma unroll
                for (int mt = 0; mt < 4; mt++)
                    ldmx4(alo[mt], aoff + APLANE + mt*(16*ASTR*2));
                #pragma unroll
                for (int mt = 0; mt < 4; mt++)
                    #pragma unroll
                    for (int nt = 0; nt < 4; nt++)
                        mma16816(d[mt][nt], alo[mt], bhi[nt]);
            }
        }
        __syncthreads();
    }
    #undef ISSUE

    // ---- epilogue ----
    #pragma unroll
    for (int mt = 0; mt < 4; mt++) {
        const int r0 = mbase + wm + mt*16 + (lane >> 2);
        #pragma unroll
        for (int nt = 0; nt < 4; nt++) {
            const int c0 = nbase + wn + nt*8 + (lane & 3)*2;
            const float b0 = bias[c0], b1 = bias[c0+1];
            #pragma unroll
            for (int half = 0; half < 2; half++) {
                const int row = r0 + half*8;
                if (row >= M) continue;
                float v0 = d[mt][nt][2*half+0] + b0;
                float v1 = d[mt][nt][2*half+1] + b1;
                if (EPI == 1) {
                    const float* rr = Res + (size_t)row * N + c0;
                    v0 += rr[0]; v1 += rr[1];
                }
                if (EPI == 2) {
                    v0 = 0.5f*v0*(1.f + erff(v0*0.70710678118654752f));
                    v1 = 0.5f*v1*(1.f + erff(v1*0.70710678118654752f));
                    __nv_bfloat16 h0 = __float2bfloat16(v0);
                    __nv_bfloat16 h1 = __float2bfloat16(v1);
                    *(uint32_t*)(Chi + (size_t)row * N + c0) = pack2(h0, h1);
                    *(uint32_t*)(Clo + (size_t)row * N + c0) =
                        pack2(__float2bfloat16(v0 - __bfloat162float(h0)),
                              __float2bfloat16(v1 - __bfloat162float(h1)));
                } else {
                    *(float2*)(C + (size_t)row * N + c0) = make_float2(v0, v1);
                }
            }
        }
    }
}

// ---------------- patch extraction -> bf16 hi/lo ----------------
__global__ void patchify_kernel(const float* __restrict__ x) {
    int idx = blockIdx.x * blockDim.x + threadIdx.x;
    if (idx >= PROWS * DIMC) return;
    int col = idx % DIMC;
    int row = idx / DIMC;
    int b   = row / NPATCH;
    int n   = row % NPATCH;
    int g1  = n / GRD, g2 = n % GRD;
    int c   = col >> 8;
    int p1  = (col >> 4) & 15;
    int p2  = col & 15;
    float v = x[((b*3 + c)*224 + g1*16 + p1)*224 + g2*16 + p2];
    __nv_bfloat16 h = __float2bfloat16(v);
    g_px_hi[idx] = h;
    g_px_lo[idx] = __float2bfloat16(v - __bfloat162float(h));
}

// ---------------- cls concat + pos embed ----------------
__global__ void embed_kernel(const float* __restrict__ cls,
                             const float* __restrict__ pos) {
    int idx = blockIdx.x * blockDim.x + threadIdx.x;
    if (idx >= BNROWS * DIMC) return;
    int d = idx % DIMC;
    int r = idx / DIMC;
    int b = r / NTOK;
    int n = r % NTOK;
    float v = (n == 0) ? cls[d] : g_pe[(b*NPATCH + n - 1)*DIMC + d];
    g_t[idx] = v + pos[n*DIMC + d];
}

// ---------------- layernorm -> bf16 hi/lo (+ optional fp32) ----------------
template<bool WF32>
__global__ __launch_bounds__(256) void ln_kernel(const float* __restrict__ in,
                                                 float* __restrict__ out,
                                                 __nv_bfloat16* __restrict__ ohi,
                                                 __nv_bfloat16* __restrict__ olo,
                                                 const float* __restrict__ gam,
                                                 const float* __restrict__ bet) {
    int row = blockIdx.x;
    const float* x = in + row*DIMC;
    float vals[3];
    float s = 0.f, s2 = 0.f;
    #pragma unroll
    for (int i = 0; i < 3; i++) {
        float v = x[threadIdx.x + i*256];
        vals[i] = v; s += v; s2 += v*v;
    }
    #pragma unroll
    for (int o = 16; o; o >>= 1) {
        s  += __shfl_xor_sync(0xffffffffu, s,  o);
        s2 += __shfl_xor_sync(0xffffffffu, s2, o);
    }
    __shared__ float red[18];
    int wid = threadIdx.x >> 5, lane = threadIdx.x & 31;
    if (lane == 0) { red[wid] = s; red[wid + 8] = s2; }
    __syncthreads();
    if (threadIdx.x < 32) {
        float a  = (lane < 8) ? red[lane]     : 0.f;
        float b2 = (lane < 8) ? red[lane + 8] : 0.f;
        #pragma unroll
        for (int o = 4; o; o >>= 1) {
            a  += __shfl_xor_sync(0xffffffffu, a,  o);
            b2 += __shfl_xor_sync(0xffffffffu, b2, o);
        }
        if (lane == 0) { red[16] = a; red[17] = b2; }
    }
    __syncthreads();
    float mean = red[16] * (1.f/768.f);
    float var  = red[17] * (1.f/768.f) - mean*mean;
    float inv  = rsqrtf(var + 1e-6f);
    #pragma unroll
    for (int i = 0; i < 3; i++) {
        int c = threadIdx.x + i*256;
        float v = (vals[i] - mean) * inv * gam[c] + bet[c];
        if (WF32) out[row*DIMC + c] = v;
        __nv_bfloat16 h = __float2bfloat16(v);
        ohi[row*DIMC + c] = h;
        olo[row*DIMC + c] = __float2bfloat16(v - __bfloat162float(h));
    }
}

// ---------------- SIMT sgemm (head only, M=32) ----------------
__global__ __launch_bounds__(256) void sgemm_kernel(
    const float* __restrict__ A, const float* __restrict__ B,
    const float* __restrict__ bias,
    float* __restrict__ C, int M, int N, int K)
{
    __shared__ float As[8][128];
    __shared__ float Bs[8][128];
    int tid = threadIdx.x;
    int bx = blockIdx.x, by = blockIdx.y;
    int tr = tid >> 4;
    int tc = tid & 15;

    float acc[8][8];
    #pragma unroll
    for (int i = 0; i < 8; i++)
        #pragma unroll
        for (int j = 0; j < 8; j++) acc[i][j] = 0.f;

    int aRow = tid >> 1;
    int aCol = (tid & 1) * 4;
    int bRow = tid >> 5;
    int bCol = (tid & 31) * 4;
    int gARow = by*128 + aRow;
    int gBCol = bx*128 + bCol;
    const float* Aptr = A + gARow*K + aCol;
    const float* Bptr = B + bRow*N + gBCol;
    bool aValid = (gARow < M);
    bool bValid = (gBCol < N);

    for (int k0 = 0; k0 < K; k0 += 8) {
        float4 av = aValid ? *(const float4*)(Aptr + k0)
                           : make_float4(0.f,0.f,0.f,0.f);
        float4 bv = bValid ? *(const float4*)(Bptr + k0*N)
                           : make_float4(0.f,0.f,0.f,0.f);
        As[aCol+0][aRow] = av.x;
        As[aCol+1][aRow] = av.y;
        As[aCol+2][aRow] = av.z;
        As[aCol+3][aRow] = av.w;
        *(float4*)&Bs[bRow][bCol] = bv;
        __syncthreads();
        #pragma unroll
        for (int kk = 0; kk < 8; kk++) {
            float a[8], b[8];
            #pragma unroll
            for (int i = 0; i < 8; i++) a[i] = As[kk][tr*8 + i];
            #pragma unroll
            for (int j = 0; j < 8; j++) b[j] = Bs[kk][tc*8 + j];
            #pragma unroll
            for (int i = 0; i < 8; i++)
                #pragma unroll
                for (int j = 0; j < 8; j++)
                    acc[i][j] += a[i] * b[j];
        }
        __syncthreads();
    }

    #pragma unroll
    for (int i = 0; i < 8; i++) {
        int row = by*128 + tr*8 + i;
        if (row >= M) continue;
        #pragma unroll
        for (int j = 0; j < 8; j++) {
            int col = bx*128 + tc*8 + j;
            if (col >= N) continue;
            C[row*N + col] = acc[i][j] + bias[col];
        }
    }
}

// ---------------- attention (optimized SIMT) ----------------
#define KTSTR 202
#define ATTN_F (64*KTSTR + NTOK*64 + 8*200 + 8*64)
#define ATTN_SMEM (ATTN_F*4)

__global__ __launch_bounds__(256, 2) void attention_kernel(const float* __restrict__ mask) {
    extern __shared__ float sm[];
    float* Kt = sm;                    // 64 x KTSTR
    float* Vs = Kt + 64*KTSTR;         // 197 rows x 64 floats (float2-paired)
    float* Ps = Vs + NTOK*64;          // 8 x 200
    float* Qs = Ps + 8*200;            // 8 x 64

    int bh = blockIdx.x;
    int b = bh / HEADS, h = bh % HEADS;
    int tid = threadIdx.x, warp = tid >> 5, lane = tid & 31;
    const float scale = 0.125f;
    int base = (b*NTOK)*H3 + h*HDIM;

    for (int idx = tid; idx < NTOK*HDIM; idx += 256) {
        int j = idx >> 6, d = idx & 63;
        Kt[d*KTSTR + j] = g_qkv[base + j*H3 + DIMC + d];
        Vs[j*64 + (d & 31)*2 + (d >> 5)] = g_qkv[base + j*H3 + 2*DIMC + d];
    }
    __syncthreads();

    for (int r = warp; r < NTOK; r += 8) {
        Qs[warp*64 + lane]      = g_qkv[base + r*H3 + lane];
        Qs[warp*64 + lane + 32] = g_qkv[base + r*H3 + lane + 32];
        __syncwarp();
        float q[64];
        #pragma unroll
        for (int d = 0; d < 64; d++) q[d] = Qs[warp*64 + d];

        float2 sp[4];
        float mx = -1e30f;
        #pragma unroll
        for (int jj = 0; jj < 4; jj++) {
            int j0 = jj*64 + 2*lane;
            bool v0 = j0 < NTOK, v1 = (j0 + 1) < NTOK;
            float s0 = -1e30f, s1 = -1e30f;
            if (v0) {
                float a0 = 0.f, a1 = 0.f;
                #pragma unroll
                for (int d = 0; d < 64; d++) {
                    float2 kk = *(const float2*)(Kt + d*KTSTR + j0);
                    a0 += q[d] * kk.x;
                    a1 += q[d] * kk.y;
                }
                s0 = a0 * scale * mask[r*NTOK + j0];
                mx = fmaxf(mx, s0);
                if (v1) {
                    s1 = a1 * scale * mask[r*NTOK + j0 + 1];
                    mx = fmaxf(mx, s1);
                }
            }
            sp[jj] = make_float2(s0, s1);
        }
        #pragma unroll
        for (int o = 16; o; o >>= 1)
            mx = fmaxf(mx, __shfl_xor_sync(0xffffffffu, mx, o));

        float sum = 0.f;
        #pragma unroll
        for (int jj = 0; jj < 4; jj++) {
            float p0 = expf(sp[jj].x - mx);
            float p1 = expf(sp[jj].y - mx);
            sp[jj] = make_float2(p0, p1);
            sum += p0 + p1;
        }
        #pragma unroll
        for (int o = 16; o; o >>= 1)
            sum += __shfl_xor_sync(0xffffffffu, sum, o);
        float rinv = 1.f / sum;

        #pragma unroll
        for (int jj = 0; jj < 4; jj++) {
            int j0 = jj*64 + 2*lane;
            if (j0 < NTOK)     Ps[warp*200 + j0]     = sp[jj].x * rinv;
            if (j0 + 1 < NTOK) Ps[warp*200 + j0 + 1] = sp[jj].y * rinv;
        }
        __syncwarp();

        float o0 = 0.f, o1 = 0.f;
        #pragma unroll 4
        for (int j = 0; j < NTOK; j++) {
            float p = Ps[warp*200 + j];
            float2 vv = *(const float2*)(Vs + j*64 + 2*lane);
            o0 += p * vv.x;
            o1 += p * vv.y;
        }
        int orow = (b*NTOK + r)*DIMC + h*HDIM;
        __nv_bfloat16 h0 = __float2bfloat16(o0);
        __nv_bfloat16 h1 = __float2bfloat16(o1);
        g_ao_hi[orow + lane]      = h0;
        g_ao_hi[orow + lane + 32] = h1;
        g_ao_lo[orow + lane]      = __float2bfloat16(o0 - __bfloat162float(h0));
        g_ao_lo[orow + lane + 32] = __float2bfloat16(o1 - __bfloat162float(h1));
    }
}

// ---------------- gather cls rows ----------------
__global__ void gather_cls_kernel() {
    int idx = blockIdx.x * blockDim.x + threadIdx.x;
    if (idx >= BATCH * DIMC) return;
    int b = idx / DIMC, d = idx % DIMC;
    g_pooled[idx] = g_h[(b*NTOK)*DIMC + d];
}

// ---------------- host driver ----------------
static inline dim3 tc_grid(int M, int N) {
    return dim3(N / 128, (M + 127) / 128);
}

#define SYMADDR(var, sym) cudaGetSymbolAddress((void**)&var, sym)

extern "C" void kernel_launch(void* const* d_in, const int* in_sizes, int n_in,
                              void* d_out, int out_size) {
    (void)in_sizes; (void)n_in; (void)out_size;
    const float* x       = (const float*)d_in[0];
    const float* cp_mask = (const float*)d_in[1];
    const float* patch_w = (const float*)d_in[2];
    const float* patch_b = (const float*)d_in[3];
    const float* cls     = (const float*)d_in[4];
    const float* pos     = (const float*)d_in[5];
    const float* ln1_g   = (const float*)d_in[6];
    const float* ln1_b   = (const float*)d_in[7];
    const float* qkv_w   = (const float*)d_in[8];
    const float* qkv_b   = (const float*)d_in[9];
    const float* proj_w  = (const float*)d_in[10];
    const float* proj_b  = (const float*)d_in[11];
    const float* ln2_g   = (const float*)d_in[12];
    const float* ln2_b   = (const float*)d_in[13];
    const float* fc1_w   = (const float*)d_in[14];
    const float* fc1_b   = (const float*)d_in[15];
    const float* fc2_w   = (const float*)d_in[16];
    const float* fc2_b   = (const float*)d_in[17];
    const float* normf_g = (const float*)d_in[18];
    const float* normf_b = (const float*)d_in[19];
    const float* head_w  = (const float*)d_in[20];
    const float* head_b  = (const float*)d_in[21];
    float* out = (float*)d_out;

    float *p_pe, *p_t, *p_h, *p_qkv, *p_pooled;
    SYMADDR(p_pe, g_pe); SYMADDR(p_t, g_t); SYMADDR(p_h, g_h);
    SYMADDR(p_qkv, g_qkv); SYMADDR(p_pooled, g_pooled);

    __nv_bfloat16 *px_hi, *px_lo, *h_hi, *h_lo, *ao_hi, *ao_lo, *ml_hi, *ml_lo;
    SYMADDR(px_hi, g_px_hi); SYMADDR(px_lo, g_px_lo);
    SYMADDR(h_hi, g_h_hi);   SYMADDR(h_lo, g_h_lo);
    SYMADDR(ao_hi, g_ao_hi); SYMADDR(ao_lo, g_ao_lo);
    SYMADDR(ml_hi, g_ml_hi); SYMADDR(ml_lo, g_ml_lo);

    __nv_bfloat16 *pe_hi, *pe_lo, *qk_hi, *qk_lo, *pr_hi, *pr_lo,
                  *f1_hi, *f1_lo, *f2_hi, *f2_lo;
    SYMADDR(pe_hi, wpe_hi); SYMADDR(pe_lo, wpe_lo);
    SYMADDR(qk_hi, wqk_hi); SYMADDR(qk_lo, wqk_lo);
    SYMADDR(pr_hi, wpr_hi); SYMADDR(pr_lo, wpr_lo);
    SYMADDR(f1_hi, wf1_hi); SYMADDR(f1_lo, wf1_lo);
    SYMADDR(f2_hi, wf2_hi); SYMADDR(f2_lo, wf2_lo);

    cudaFuncSetAttribute(attention_kernel,
                         cudaFuncAttributeMaxDynamicSharedMemorySize, (int)ATTN_SMEM);
    cudaFuncSetAttribute(hmma_gemm<0>,
                         cudaFuncAttributeMaxDynamicSharedMemorySize, HM_SMEM);
    cudaFuncSetAttribute(hmma_gemm<1>,
                         cudaFuncAttributeMaxDynamicSharedMemorySize, HM_SMEM);
    cudaFuncSetAttribute(hmma_gemm<2>,
                         cudaFuncAttributeMaxDynamicSharedMemorySize, HM_SMEM);

    // ---- weight pre-conversion (bulk, once per launch) ----
    {
        int n4;
        n4 = (DIMC*DIMC)/4;
        convert_w<<<(n4+255)/256, 256>>>(patch_w, pe_hi, pe_lo, n4);
        n4 = (DEPTH*DIMC*H3)/4;
        convert_w<<<(n4+255)/256, 256>>>(qkv_w, qk_hi, qk_lo, n4);
        n4 = (DEPTH*DIMC*DIMC)/4;
        convert_w<<<(n4+255)/256, 256>>>(proj_w, pr_hi, pr_lo, n4);
        n4 = (DEPTH*DIMC*MLPD)/4;
        convert_w<<<(n4+255)/256, 256>>>(fc1_w, f1_hi, f1_lo, n4);
        n4 = (DEPTH*MLPD*DIMC)/4;
        convert_w<<<(n4+255)/256, 256>>>(fc2_w, f2_hi, f2_lo, n4);
    }

    patchify_kernel<<<(PROWS*DIMC + 255)/256, 256>>>(x);
    hmma_gemm<0><<<tc_grid(PROWS, DIMC), 256, HM_SMEM>>>(
        px_hi, px_lo, pe_hi, pe_lo, patch_b, nullptr,
        p_pe, nullptr, nullptr, PROWS, DIMC, DIMC);
    embed_kernel<<<(BNROWS*DIMC + 255)/256, 256>>>(cls, pos);

    for (int i = 0; i < DEPTH; i++) {
        ln_kernel<false><<<BNROWS, 256>>>(p_t, nullptr, h_hi, h_lo,
                                          ln1_g + i*DIMC, ln1_b + i*DIMC);
        hmma_gemm<0><<<tc_grid(BNROWS, H3), 256, HM_SMEM>>>(
            h_hi, h_lo, qk_hi + (size_t)i*DIMC*H3, qk_lo + (size_t)i*DIMC*H3,
            qkv_b + i*H3, nullptr, p_qkv, nullptr, nullptr, BNROWS, H3, DIMC);
        attention_kernel<<<BATCH*HEADS, 256, ATTN_SMEM>>>(cp_mask);
        hmma_gemm<1><<<tc_grid(BNROWS, DIMC), 256, HM_SMEM>>>(
            ao_hi, ao_lo, pr_hi + (size_t)i*DIMC*DIMC, pr_lo + (size_t)i*DIMC*DIMC,
            proj_b + i*DIMC, p_t, p_t, nullptr, nullptr, BNROWS, DIMC, DIMC);
        ln_kernel<false><<<BNROWS, 256>>>(p_t, nullptr, h_hi, h_lo,
                                          ln2_g + i*DIMC, ln2_b + i*DIMC);
        hmma_gemm<2><<<tc_grid(BNROWS, MLPD), 256, HM_SMEM>>>(
            h_hi, h_lo, f1_hi + (size_t)i*DIMC*MLPD, f1_lo + (size_t)i*DIMC*MLPD,
            fc1_b + i*MLPD, nullptr, nullptr, ml_hi, ml_lo, BNROWS, MLPD, DIMC);
        hmma_gemm<1><<<tc_grid(BNROWS, DIMC), 256, HM_SMEM>>>(
            ml_hi, ml_lo, f2_hi + (size_t)i*MLPD*DIMC, f2_lo + (size_t)i*MLPD*DIMC,
            fc2_b + i*DIMC, p_t, p_t, nullptr, nullptr, BNROWS, DIMC, MLPD);
    }

    ln_kernel<true><<<BNROWS, 256>>>(p_t, p_h, h_hi, h_lo, normf_g, normf_b);
    gather_cls_kernel<<<(BATCH*DIMC + 255)/256, 256>>>();
    sgemm_kernel<<<dim3((NCLS + 127)/128, 1), 256>>>(
        p_pooled, head_w, head_b, out, BATCH, NCLS, DIMC);
}

// round 13
// speedup vs baseline: 1.6086x; 1.0722x over previous
#include <cuda_runtime.h>
#include <cuda_bf16.h>
#include <math.h>
#include <stdint.h>

// ---------------- problem constants ----------------
#define DEPTH   12
#define DIMC    768
#define HEADS   12
#define MLPD    3072
#define NCLS    1000
#define NTOK    197
#define NPATCH  196
#define BATCH   32
#define HDIM    64
#define GRD     14
#define BNROWS  (BATCH*NTOK)     // 6304
#define PROWS   (BATCH*NPATCH)   // 6272
#define H3      (3*DIMC)         // 2304

// ---------------- scratch (fp32) ----------------
__device__ float g_pe[PROWS*DIMC];
__device__ float g_t[BNROWS*DIMC];
__device__ float g_h[BNROWS*DIMC];
__device__ float g_qkv[BNROWS*H3];
__device__ float g_pooled[BATCH*DIMC];

// ---------------- scratch (bf16 hi/lo activation planes) ----------------
__device__ __nv_bfloat16 g_px_hi[PROWS*DIMC],  g_px_lo[PROWS*DIMC];
__device__ __nv_bfloat16 g_h_hi[BNROWS*DIMC],  g_h_lo[BNROWS*DIMC];
__device__ __nv_bfloat16 g_ao_hi[BNROWS*DIMC], g_ao_lo[BNROWS*DIMC];
__device__ __nv_bfloat16 g_ml_hi[BNROWS*MLPD], g_ml_lo[BNROWS*MLPD];

// ---------------- scratch (bf16 hi/lo weight planes) ----------------
__device__ __nv_bfloat16 wpe_hi[DIMC*DIMC],       wpe_lo[DIMC*DIMC];
__device__ __nv_bfloat16 wqk_hi[DEPTH*DIMC*H3],   wqk_lo[DEPTH*DIMC*H3];
__device__ __nv_bfloat16 wpr_hi[DEPTH*DIMC*DIMC], wpr_lo[DEPTH*DIMC*DIMC];
__device__ __nv_bfloat16 wf1_hi[DEPTH*DIMC*MLPD], wf1_lo[DEPTH*DIMC*MLPD];
__device__ __nv_bfloat16 wf2_hi[DEPTH*MLPD*DIMC], wf2_lo[DEPTH*MLPD*DIMC];

// ---------------- helpers ----------------
__device__ __forceinline__ uint32_t smem_u32(const void* p) {
    uint32_t a;
    asm("{ .reg .u64 t; cvta.to.shared.u64 t, %1; cvt.u32.u64 %0, t; }"
        : "=r"(a) : "l"(p));
    return a;
}
__device__ __forceinline__ uint32_t pack2(__nv_bfloat16 a, __nv_bfloat16 b) {
    return (uint32_t)__bfloat16_as_ushort(a) |
           ((uint32_t)__bfloat16_as_ushort(b) << 16);
}
__device__ __forceinline__ void ldmx4(uint32_t* r, uint32_t addr) {
    asm volatile("ldmatrix.sync.aligned.m8n8.x4.shared.b16 {%0,%1,%2,%3}, [%4];"
        : "=r"(r[0]), "=r"(r[1]), "=r"(r[2]), "=r"(r[3]) : "r"(addr));
}
__device__ __forceinline__ void ldmx4t(uint32_t* r, uint32_t addr) {
    asm volatile("ldmatrix.sync.aligned.m8n8.x4.trans.shared.b16 {%0,%1,%2,%3}, [%4];"
        : "=r"(r[0]), "=r"(r[1]), "=r"(r[2]), "=r"(r[3]) : "r"(addr));
}
__device__ __forceinline__ void mma16816(float* d, const uint32_t* a, const uint32_t* b) {
    asm volatile(
        "mma.sync.aligned.m16n8k16.row.col.f32.bf16.bf16.f32 "
        "{%0,%1,%2,%3}, {%4,%5,%6,%7}, {%8,%9}, {%0,%1,%2,%3};"
        : "+f"(d[0]), "+f"(d[1]), "+f"(d[2]), "+f"(d[3])
        : "r"(a[0]), "r"(a[1]), "r"(a[2]), "r"(a[3]), "r"(b[0]), "r"(b[1]));
}
__device__ __forceinline__ void cpa16(uint32_t dst, const void* src, bool ok) {
    asm volatile("cp.async.cg.shared.global [%0], [%1], 16, %2;"
                 :: "r"(dst), "l"(src), "r"(ok ? 16 : 0) : "memory");
}

// ---------------- smem layout per stage (bf16 units) ----------------
#define ASTR    40
#define BSTR    136
#define APLANE  10240
#define BOFF    20480
#define BPLANE  8704
#define BUFSZ   37888
#define NSTG    3
#define HM_SMEM (NSTG*BUFSZ)   // 113664 B; 2 CTAs = 227.3KB <= 228KB

// ---------------- weight conversion: fp32 -> bf16 hi/lo ----------------
__global__ void convert_w(const float* __restrict__ src,
                          __nv_bfloat16* __restrict__ hi,
                          __nv_bfloat16* __restrict__ lo, int n4) {
    int i = blockIdx.x * blockDim.x + threadIdx.x;
    if (i >= n4) return;
    float4 v = *(const float4*)(src + i*4);
    __nv_bfloat16 h0=__float2bfloat16(v.x), h1=__float2bfloat16(v.y);
    __nv_bfloat16 h2=__float2bfloat16(v.z), h3=__float2bfloat16(v.w);
    *(uint32_t*)(hi + i*4)     = pack2(h0, h1);
    *(uint32_t*)(hi + i*4 + 2) = pack2(h2, h3);
    *(uint32_t*)(lo + i*4)     = pack2(__float2bfloat16(v.x-__bfloat162float(h0)),
                                       __float2bfloat16(v.y-__bfloat162float(h1)));
    *(uint32_t*)(lo + i*4 + 2) = pack2(__float2bfloat16(v.z-__bfloat162float(h2)),
                                       __float2bfloat16(v.w-__bfloat162float(h3)));
}

// ============ bf16 3-split mma.sync GEMM (K-chunk 32, 3-stage) ============
// EPI: 0=bias->f32, 1=bias+residual->f32, 2=bias+GELU->bf16 hi/lo planes
template<int EPI>
__global__ __launch_bounds__(256, 2) void hmma_gemm(
    const __nv_bfloat16* __restrict__ Ahi, const __nv_bfloat16* __restrict__ Alo,
    const __nv_bfloat16* __restrict__ Whi, const __nv_bfloat16* __restrict__ Wlo,
    const float* __restrict__ bias, const float* __restrict__ Res,
    float* __restrict__ C,
    __nv_bfloat16* __restrict__ Chi, __nv_bfloat16* __restrict__ Clo,
    int M, int N, int K)
{
    extern __shared__ char smem[];
    const uint32_t sb = smem_u32(smem);
    const int tid  = threadIdx.x;
    const int warp = tid >> 5;
    const int lane = tid & 31;
    const int mbase = blockIdx.y * 128;
    const int nbase = blockIdx.x * 128;

    const int wm = (warp & 1) * 64;
    const int wn = (warp >> 1) * 32;

    float d[4][4][4];
    #pragma unroll
    for (int i = 0; i < 4; i++)
        #pragma unroll
        for (int j = 0; j < 4; j++)
            #pragma unroll
            for (int r = 0; r < 4; r++) d[i][j][r] = 0.f;

    const int nch = K >> 5;

    #define ISSUE(c, bsel) do {                                               \
        const uint32_t dbase = sb + (uint32_t)(bsel) * BUFSZ;                 \
        const int k0 = (c) << 5;                                              \
        _Pragma("unroll")                                                     \
        for (int i = 0; i < 4; i++) {                                         \
            int t = tid + i*256;                                              \
            int p = t >> 9, idx = t & 511;                                    \
            int row = idx >> 2, seg = idx & 3;                                \
            bool ok = (mbase + row) < M;                                      \
            const __nv_bfloat16* sp = (p ? Alo : Ahi);                        \
            const __nv_bfloat16* src = ok ? sp + (size_t)(mbase+row)*K + k0 + seg*8 : sp; \
            cpa16(dbase + (uint32_t)(p*APLANE + row*80 + seg*16), src, ok);   \
        }                                                                     \
        _Pragma("unroll")                                                     \
        for (int i = 0; i < 4; i++) {                                         \
            int t = tid + i*256;                                              \
            int p = t >> 9, idx = t & 511;                                    \
            int row = idx >> 4, seg = idx & 15;                               \
            const __nv_bfloat16* src = (p ? Wlo : Whi) + (size_t)(k0+row)*N + nbase + seg*8; \
            cpa16(dbase + (uint32_t)(BOFF + p*BPLANE + row*272 + seg*16), src, true); \
        }                                                                     \
        asm volatile("cp.async.commit_group;" ::: "memory");                  \
    } while (0)

    ISSUE(0, 0);
    ISSUE(1, 1);

    int bsel = 0, bnext = 2;
    for (int c = 0; c < nch; ++c) {
        if (c + 2 < nch) {
            ISSUE(c + 2, bnext);
            asm volatile("cp.async.wait_group 2;" ::: "memory");
        } else if (c + 1 < nch) {
            asm volatile("cp.async.wait_group 1;" ::: "memory");
        } else {
            asm volatile("cp.async.wait_group 0;" ::: "memory");
        }
        __syncthreads();

        const uint32_t sbuf = sb + (uint32_t)bsel * BUFSZ;
        bnext = bsel;
        bsel = (bsel + 1 == NSTG) ? 0 : bsel + 1;

        #pragma unroll
        for (int ks = 0; ks < 2; ++ks) {
            const uint32_t aoff = sbuf +
                (uint32_t)((wm + (lane & 15))*ASTR + ks*16 + (lane >> 4)*8) * 2;
            const uint32_t boff = sbuf + BOFF +
                (uint32_t)((ks*16 + (lane & 15))*BSTR + wn + (lane >> 4)*8) * 2;

            uint32_t ahi[4][4], bhi[4][2];
            #pragma unroll
            for (int mt = 0; mt < 4; mt++) ldmx4(ahi[mt], aoff + mt*(16*ASTR*2));
            #pragma unroll
            for (int ng = 0; ng < 2; ng++) {
                uint32_t r[4];
                ldmx4t(r, boff + ng*32);
                bhi[2*ng][0]   = r[0]; bhi[2*ng][1]   = r[1];
                bhi[2*ng+1][0] = r[2]; bhi[2*ng+1][1] = r[3];
            }
            #pragma unroll
            for (int mt = 0; mt < 4; mt++)
                #pragma unroll
                for (int nt = 0; nt < 4; nt++)
                    mma16816(d[mt][nt], ahi[mt], bhi[nt]);

            {
                uint32_t blo[4][2];
                #pragma unroll
                for (int ng = 0; ng < 2; ng++) {
                    uint32_t r[4];
                    ldmx4t(r, boff + BPLANE + ng*32);
                    blo[2*ng][0]   = r[0]; blo[2*ng][1]   = r[1];
                    blo[2*ng+1][0] = r[2]; blo[2*ng+1][1] = r[3];
                }
                #pragma unroll
                for (int mt = 0; mt < 4; mt++)
                    #pragma unroll
                    for (int nt = 0; nt < 4; nt++)
                        mma16816(d[mt][nt], ahi[mt], blo[nt]);
            }
            {
                uint32_t alo[4][4];
                #pragma unroll
                for (int mt = 0; mt < 4; mt++)
                    ldmx4(alo[mt], aoff + APLANE + mt*(16*ASTR*2));
                #pragma unroll
                for (int mt = 0; mt < 4; mt++)
                    #pragma unroll
                    for (int nt = 0; nt < 4; nt++)
                        mma16816(d[mt][nt], alo[mt], bhi[nt]);
            }
        }
        __syncthreads();
    }
    #undef ISSUE

    // ---- epilogue ----
    #pragma unroll
    for (int mt = 0; mt < 4; mt++) {
        const int r0 = mbase + wm + mt*16 + (lane >> 2);
        #pragma unroll
        for (int nt = 0; nt < 4; nt++) {
            const int c0 = nbase + wn + nt*8 + (lane & 3)*2;
            const float b0 = bias[c0], b1 = bias[c0+1];
            #pragma unroll
            for (int half = 0; half < 2; half++) {
                const int row = r0 + half*8;
                if (row >= M) continue;
                float v0 = d[mt][nt][2*half+0] + b0;
                float v1 = d[mt][nt][2*half+1] + b1;
                if (EPI == 1) {
                    const float* rr = Res + (size_t)row * N + c0;
                    v0 += rr[0]; v1 += rr[1];
                }
                if (EPI == 2) {
                    v0 = 0.5f*v0*(1.f + erff(v0*0.70710678118654752f));
                    v1 = 0.5f*v1*(1.f + erff(v1*0.70710678118654752f));
                    __nv_bfloat16 h0 = __float2bfloat16(v0);
                    __nv_bfloat16 h1 = __float2bfloat16(v1);
                    *(uint32_t*)(Chi + (size_t)row * N + c0) = pack2(h0, h1);
                    *(uint32_t*)(Clo + (size_t)row * N + c0) =
                        pack2(__float2bfloat16(v0 - __bfloat162float(h0)),
                              __float2bfloat16(v1 - __bfloat162float(h1)));
                } else {
                    *(float2*)(C + (size_t)row * N + c0) = make_float2(v0, v1);
                }
            }
        }
    }
}

// ---------------- patch extraction -> bf16 hi/lo ----------------
__global__ void patchify_kernel(const float* __restrict__ x) {
    int idx = blockIdx.x * blockDim.x + threadIdx.x;
    if (idx >= PROWS * DIMC) return;
    int col = idx % DIMC;
    int row = idx / DIMC;
    int b   = row / NPATCH;
    int n   = row % NPATCH;
    int g1  = n / GRD, g2 = n % GRD;
    int c   = col >> 8;
    int p1  = (col >> 4) & 15;
    int p2  = col & 15;
    float v = x[((b*3 + c)*224 + g1*16 + p1)*224 + g2*16 + p2];
    __nv_bfloat16 h = __float2bfloat16(v);
    g_px_hi[idx] = h;
    g_px_lo[idx] = __float2bfloat16(v - __bfloat162float(h));
}

// ---------------- cls concat + pos embed ----------------
__global__ void embed_kernel(const float* __restrict__ cls,
                             const float* __restrict__ pos) {
    int idx = blockIdx.x * blockDim.x + threadIdx.x;
    if (idx >= BNROWS * DIMC) return;
    int d = idx % DIMC;
    int r = idx / DIMC;
    int b = r / NTOK;
    int n = r % NTOK;
    float v = (n == 0) ? cls[d] : g_pe[(b*NPATCH + n - 1)*DIMC + d];
    g_t[idx] = v + pos[n*DIMC + d];
}

// ---------------- layernorm -> bf16 hi/lo (+ optional fp32) ----------------
template<bool WF32>
__global__ __launch_bounds__(256) void ln_kernel(const float* __restrict__ in,
                                                 float* __restrict__ out,
                                                 __nv_bfloat16* __restrict__ ohi,
                                                 __nv_bfloat16* __restrict__ olo,
                                                 const float* __restrict__ gam,
                                                 const float* __restrict__ bet) {
    int row = blockIdx.x;
    const float* x = in + row*DIMC;
    float vals[3];
    float s = 0.f, s2 = 0.f;
    #pragma unroll
    for (int i = 0; i < 3; i++) {
        float v = x[threadIdx.x + i*256];
        vals[i] = v; s += v; s2 += v*v;
    }
    #pragma unroll
    for (int o = 16; o; o >>= 1) {
        s  += __shfl_xor_sync(0xffffffffu, s,  o);
        s2 += __shfl_xor_sync(0xffffffffu, s2, o);
    }
    __shared__ float red[18];
    int wid = threadIdx.x >> 5, lane = threadIdx.x & 31;
    if (lane == 0) { red[wid] = s; red[wid + 8] = s2; }
    __syncthreads();
    if (threadIdx.x < 32) {
        float a  = (lane < 8) ? red[lane]     : 0.f;
        float b2 = (lane < 8) ? red[lane + 8] : 0.f;
        #pragma unroll
        for (int o = 4; o; o >>= 1) {
            a  += __shfl_xor_sync(0xffffffffu, a,  o);
            b2 += __shfl_xor_sync(0xffffffffu, b2, o);
        }
        if (lane == 0) { red[16] = a; red[17] = b2; }
    }
    __syncthreads();
    float mean = red[16] * (1.f/768.f);
    float var  = red[17] * (1.f/768.f) - mean*mean;
    float inv  = rsqrtf(var + 1e-6f);
    #pragma unroll
    for (int i = 0; i < 3; i++) {
        int c = threadIdx.x + i*256;
        float v = (vals[i] - mean) * inv * gam[c] + bet[c];
        if (WF32) out[row*DIMC + c] = v;
        __nv_bfloat16 h = __float2bfloat16(v);
        ohi[row*DIMC + c] = h;
        olo[row*DIMC + c] = __float2bfloat16(v - __bfloat162float(h));
    }
}

// ---------------- SIMT sgemm (head only, M=32) ----------------
__global__ __launch_bounds__(256) void sgemm_kernel(
    const float* __restrict__ A, const float* __restrict__ B,
    const float* __restrict__ bias,
    float* __restrict__ C, int M, int N, int K)
{
    __shared__ float As[8][128];
    __shared__ float Bs[8][128];
    int tid = threadIdx.x;
    int bx = blockIdx.x, by = blockIdx.y;
    int tr = tid >> 4;
    int tc = tid & 15;

    float acc[8][8];
    #pragma unroll
    for (int i = 0; i < 8; i++)
        #pragma unroll
        for (int j = 0; j < 8; j++) acc[i][j] = 0.f;

    int aRow = tid >> 1;
    int aCol = (tid & 1) * 4;
    int bRow = tid >> 5;
    int bCol = (tid & 31) * 4;
    int gARow = by*128 + aRow;
    int gBCol = bx*128 + bCol;
    const float* Aptr = A + gARow*K + aCol;
    const float* Bptr = B + bRow*N + gBCol;
    bool aValid = (gARow < M);
    bool bValid = (gBCol < N);

    for (int k0 = 0; k0 < K; k0 += 8) {
        float4 av = aValid ? *(const float4*)(Aptr + k0)
                           : make_float4(0.f,0.f,0.f,0.f);
        float4 bv = bValid ? *(const float4*)(Bptr + k0*N)
                           : make_float4(0.f,0.f,0.f,0.f);
        As[aCol+0][aRow] = av.x;
        As[aCol+1][aRow] = av.y;
        As[aCol+2][aRow] = av.z;
        As[aCol+3][aRow] = av.w;
        *(float4*)&Bs[bRow][bCol] = bv;
        __syncthreads();
        #pragma unroll
        for (int kk = 0; kk < 8; kk++) {
            float a[8], b[8];
            #pragma unroll
            for (int i = 0; i < 8; i++) a[i] = As[kk][tr*8 + i];
            #pragma unroll
            for (int j = 0; j < 8; j++) b[j] = Bs[kk][tc*8 + j];
            #pragma unroll
            for (int i = 0; i < 8; i++)
                #pragma unroll
                for (int j = 0; j < 8; j++)
                    acc[i][j] += a[i] * b[j];
        }
        __syncthreads();
    }

    #pragma unroll
    for (int i = 0; i < 8; i++) {
        int row = by*128 + tr*8 + i;
        if (row >= M) continue;
        #pragma unroll
        for (int j = 0; j < 8; j++) {
            int col = bx*128 + tc*8 + j;
            if (col >= N) continue;
            C[row*N + col] = acc[i][j] + bias[col];
        }
    }
}

// ---------------- attention (optimized SIMT) ----------------
#define KTSTR 202
#define ATTN_F (64*KTSTR + NTOK*64 + 8*200 + 8*64)
#define ATTN_SMEM (ATTN_F*4)

__global__ __launch_bounds__(256, 2) void attention_kernel(const float* __restrict__ mask) {
    extern __shared__ float sm[];
    float* Kt = sm;                    // 64 x KTSTR
    float* Vs = Kt + 64*KTSTR;         // 197 rows x 64 floats (float2-paired)
    float* Ps = Vs + NTOK*64;          // 8 x 200
    float* Qs = Ps + 8*200;            // 8 x 64

    int bh = blockIdx.x;
    int b = bh / HEADS, h = bh % HEADS;
    int tid = threadIdx.x, warp = tid >> 5, lane = tid & 31;
    const float scale = 0.125f;
    int base = (b*NTOK)*H3 + h*HDIM;

    for (int idx = tid; idx < NTOK*HDIM; idx += 256) {
        int j = idx >> 6, d = idx & 63;
        Kt[d*KTSTR + j] = g_qkv[base + j*H3 + DIMC + d];
        Vs[j*64 + (d & 31)*2 + (d >> 5)] = g_qkv[base + j*H3 + 2*DIMC + d];
    }
    __syncthreads();

    for (int r = warp; r < NTOK; r += 8) {
        Qs[warp*64 + lane]      = g_qkv[base + r*H3 + lane];
        Qs[warp*64 + lane + 32] = g_qkv[base + r*H3 + lane + 32];
        __syncwarp();
        float q[64];
        #pragma unroll
        for (int d = 0; d < 64; d++) q[d] = Qs[warp*64 + d];

        float2 sp[4];
        float mx = -1e30f;
        #pragma unroll
        for (int jj = 0; jj < 4; jj++) {
            int j0 = jj*64 + 2*lane;
            bool v0 = j0 < NTOK, v1 = (j0 + 1) < NTOK;
            float s0 = -1e30f, s1 = -1e30f;
            if (v0) {
                float a0 = 0.f, a1 = 0.f;
                #pragma unroll
                for (int d = 0; d < 64; d++) {
                    float2 kk = *(const float2*)(Kt + d*KTSTR + j0);
                    a0 += q[d] * kk.x;
                    a1 += q[d] * kk.y;
                }
                s0 = a0 * scale * mask[r*NTOK + j0];
                mx = fmaxf(mx, s0);
                if (v1) {
                    s1 = a1 * scale * mask[r*NTOK + j0 + 1];
                    mx = fmaxf(mx, s1);
                }
            }
            sp[jj] = make_float2(s0, s1);
        }
        #pragma unroll
        for (int o = 16; o; o >>= 1)
            mx = fmaxf(mx, __shfl_xor_sync(0xffffffffu, mx, o));

        float sum = 0.f;
        #pragma unroll
        for (int jj = 0; jj < 4; jj++) {
            float p0 = expf(sp[jj].x - mx);
            float p1 = expf(sp[jj].y - mx);
            sp[jj] = make_float2(p0, p1);
            sum += p0 + p1;
        }
        #pragma unroll
        for (int o = 16; o; o >>= 1)
            sum += __shfl_xor_sync(0xffffffffu, sum, o);
        float rinv = 1.f / sum;

        #pragma unroll
        for (int jj = 0; jj < 4; jj++) {
            int j0 = jj*64 + 2*lane;
            if (j0 < NTOK)     Ps[warp*200 + j0]     = sp[jj].x * rinv;
            if (j0 + 1 < NTOK) Ps[warp*200 + j0 + 1] = sp[jj].y * rinv;
        }
        __syncwarp();

        float o0 = 0.f, o1 = 0.f;
        #pragma unroll 4
        for (int j = 0; j < NTOK; j++) {
            float p = Ps[warp*200 + j];
            float2 vv = *(const float2*)(Vs + j*64 + 2*lane);
            o0 += p * vv.x;
            o1 += p * vv.y;
        }
        int orow = (b*NTOK + r)*DIMC + h*HDIM;
        __nv_bfloat16 h0 = __float2bfloat16(o0);
        __nv_bfloat16 h1 = __float2bfloat16(o1);
        g_ao_hi[orow + lane]      = h0;
        g_ao_hi[orow + lane + 32] = h1;
        g_ao_lo[orow + lane]      = __float2bfloat16(o0 - __bfloat162float(h0));
        g_ao_lo[orow + lane + 32] = __float2bfloat16(o1 - __bfloat162float(h1));
    }
}

// ---------------- gather cls rows ----------------
__global__ void gather_cls_kernel() {
    int idx = blockIdx.x * blockDim.x + threadIdx.x;
    if (idx >= BATCH * DIMC) return;
    int b = idx / DIMC, d = idx % DIMC;
    g_pooled[idx] = g_h[(b*NTOK)*DIMC + d];
}

// ---------------- host driver ----------------
static inline dim3 tc_grid(int M, int N) {
    return dim3(N / 128, (M + 127) / 128);
}

#define SYMADDR(var, sym) cudaGetSymbolAddress((void**)&var, sym)

extern "C" void kernel_launch(void* const* d_in, const int* in_sizes, int n_in,
                              void* d_out, int out_size) {
    (void)in_sizes; (void)n_in; (void)out_size;
    const float* x       = (const float*)d_in[0];
    const float* cp_mask = (const float*)d_in[1];
    const float* patch_w = (const float*)d_in[2];
    const float* patch_b = (const float*)d_in[3];
    const float* cls     = (const float*)d_in[4];
    const float* pos     = (const float*)d_in[5];
    const float* ln1_g   = (const float*)d_in[6];
    const float* ln1_b   = (const float*)d_in[7];
    const float* qkv_w   = (const float*)d_in[8];
    const float* qkv_b   = (const float*)d_in[9];
    const float* proj_w  = (const float*)d_in[10];
    const float* proj_b  = (const float*)d_in[11];
    const float* ln2_g   = (const float*)d_in[12];
    const float* ln2_b   = (const float*)d_in[13];
    const float* fc1_w   = (const float*)d_in[14];
    const float* fc1_b   = (const float*)d_in[15];
    const float* fc2_w   = (const float*)d_in[16];
    const float* fc2_b   = (const float*)d_in[17];
    const float* normf_g = (const float*)d_in[18];
    const float* normf_b = (const float*)d_in[19];
    const float* head_w  = (const float*)d_in[20];
    const float* head_b  = (const float*)d_in[21];
    float* out = (float*)d_out;

    float *p_pe, *p_t, *p_h, *p_qkv, *p_pooled;
    SYMADDR(p_pe, g_pe); SYMADDR(p_t, g_t); SYMADDR(p_h, g_h);
    SYMADDR(p_qkv, g_qkv); SYMADDR(p_pooled, g_pooled);

    __nv_bfloat16 *px_hi, *px_lo, *h_hi, *h_lo, *ao_hi, *ao_lo, *ml_hi, *ml_lo;
    SYMADDR(px_hi, g_px_hi); SYMADDR(px_lo, g_px_lo);
    SYMADDR(h_hi, g_h_hi);   SYMADDR(h_lo, g_h_lo);
    SYMADDR(ao_hi, g_ao_hi); SYMADDR(ao_lo, g_ao_lo);
    SYMADDR(ml_hi, g_ml_hi); SYMADDR(ml_lo, g_ml_lo);

    __nv_bfloat16 *pe_hi, *pe_lo, *qk_hi, *qk_lo, *pr_hi, *pr_lo,
                  *f1_hi, *f1_lo, *f2_hi, *f2_lo;
    SYMADDR(pe_hi, wpe_hi); SYMADDR(pe_lo, wpe_lo);
    SYMADDR(qk_hi, wqk_hi); SYMADDR(qk_lo, wqk_lo);
    SYMADDR(pr_hi, wpr_hi); SYMADDR(pr_lo, wpr_lo);
    SYMADDR(f1_hi, wf1_hi); SYMADDR(f1_lo, wf1_lo);
    SYMADDR(f2_hi, wf2_hi); SYMADDR(f2_lo, wf2_lo);

    cudaFuncSetAttribute(attention_kernel,
                         cudaFuncAttributeMaxDynamicSharedMemorySize, (int)ATTN_SMEM);
    cudaFuncSetAttribute(hmma_gemm<0>,
                         cudaFuncAttributeMaxDynamicSharedMemorySize, HM_SMEM);
    cudaFuncSetAttribute(hmma_gemm<1>,
                         cudaFuncAttributeMaxDynamicSharedMemorySize, HM_SMEM);
    cudaFuncSetAttribute(hmma_gemm<2>,
                         cudaFuncAttributeMaxDynamicSharedMemorySize, HM_SMEM);

    // ---- weight pre-conversion (bulk, once per launch) ----
    {
        int n4;
        n4 = (DIMC*DIMC)/4;
        convert_w<<<(n4+255)/256, 256>>>(patch_w, pe_hi, pe_lo, n4);
        n4 = (DEPTH*DIMC*H3)/4;
        convert_w<<<(n4+255)/256, 256>>>(qkv_w, qk_hi, qk_lo, n4);
        n4 = (DEPTH*DIMC*DIMC)/4;
        convert_w<<<(n4+255)/256, 256>>>(proj_w, pr_hi, pr_lo, n4);
        n4 = (DEPTH*DIMC*MLPD)/4;
        convert_w<<<(n4+255)/256, 256>>>(fc1_w, f1_hi, f1_lo, n4);
        n4 = (DEPTH*MLPD*DIMC)/4;
        convert_w<<<(n4+255)/256, 256>>>(fc2_w, f2_hi, f2_lo, n4);
    }

    patchify_kernel<<<(PROWS*DIMC + 255)/256, 256>>>(x);
    hmma_gemm<0><<<tc_grid(PROWS, DIMC), 256, HM_SMEM>>>(
        px_hi, px_lo, pe_hi, pe_lo, patch_b, nullptr,
        p_pe, nullptr, nullptr, PROWS, DIMC, DIMC);
    embed_kernel<<<(BNROWS*DIMC + 255)/256, 256>>>(cls, pos);

    for (int i = 0; i < DEPTH; i++) {
        ln_kernel<false><<<BNROWS, 256>>>(p_t, nullptr, h_hi, h_lo,
                                          ln1_g + i*DIMC, ln1_b + i*DIMC);
        hmma_gemm<0><<<tc_grid(BNROWS, H3), 256, HM_SMEM>>>(
            h_hi, h_lo, qk_hi + (size_t)i*DIMC*H3, qk_lo + (size_t)i*DIMC*H3,
            qkv_b + i*H3, nullptr, p_qkv, nullptr, nullptr, BNROWS, H3, DIMC);
        attention_kernel<<<BATCH*HEADS, 256, ATTN_SMEM>>>(cp_mask);
        hmma_gemm<1><<<tc_grid(BNROWS, DIMC), 256, HM_SMEM>>>(
            ao_hi, ao_lo, pr_hi + (size_t)i*DIMC*DIMC, pr_lo + (size_t)i*DIMC*DIMC,
            proj_b + i*DIMC, p_t, p_t, nullptr, nullptr, BNROWS, DIMC, DIMC);
        ln_kernel<false><<<BNROWS, 256>>>(p_t, nullptr, h_hi, h_lo,
                                          ln2_g + i*DIMC, ln2_b + i*DIMC);
        hmma_gemm<2><<<tc_grid(BNROWS, MLPD), 256, HM_SMEM>>>(
            h_hi, h_lo, f1_hi + (size_t)i*DIMC*MLPD, f1_lo + (size_t)i*DIMC*MLPD,
            fc1_b + i*MLPD, nullptr, nullptr, ml_hi, ml_lo, BNROWS, MLPD, DIMC);
        hmma_gemm<1><<<tc_grid(BNROWS, DIMC), 256, HM_SMEM>>>(
            ml_hi, ml_lo, f2_hi + (size_t)i*MLPD*DIMC, f2_lo + (size_t)i*MLPD*DIMC,
            fc2_b + i*DIMC, p_t, p_t, nullptr, nullptr, BNROWS, DIMC, MLPD);
    }

    ln_kernel<true><<<BNROWS, 256>>>(p_t, p_h, h_hi, h_lo, normf_g, normf_b);
    gather_cls_kernel<<<(BATCH*DIMC + 255)/256, 256>>>();
    sgemm_kernel<<<dim3((NCLS + 127)/128, 1), 256>>>(
        p_pooled, head_w, head_b, out, BATCH, NCLS, DIMC);
}